// round 3
// baseline (speedup 1.0000x reference)
#include <cuda_runtime.h>
#include <cstdint>

#define NN 100000
#define EE 1600000
#define DD 128

// ---------------- scratch (device globals; no runtime allocation) ----------------
__device__ float g_bufA[(size_t)NN * DD];
__device__ float g_bufB[(size_t)NN * DD];
__device__ float g_bufC[(size_t)NN * DD];
__device__ int   g_counts[NN];
__device__ int   g_off[NN + 1];
__device__ int   g_cursor[NN];
__device__ int   g_bsums[128];
__device__ float g_dinv[NN];
__device__ int   g_src[EE];
__device__ float g_wt[EE];
__device__ float g_colsum[DD];
__device__ float g_colsq[DD];
__device__ float g_scale[DD];
__device__ float g_shift[DD];

// ---------------- graph preprocessing ----------------

__global__ void zero_counts_k() {
    int i = blockIdx.x * blockDim.x + threadIdx.x;
    if (i < NN) g_counts[i] = 0;
}

__global__ void zero_stats_k() {
    int t = threadIdx.x;
    if (t < DD) { g_colsum[t] = 0.0f; g_colsq[t] = 0.0f; }
}

__global__ void hist_k(const int* __restrict__ colp) {
    int i = blockIdx.x * blockDim.x + threadIdx.x;
    int stride = gridDim.x * blockDim.x;
    for (; i < EE; i += stride) atomicAdd(&g_counts[colp[i]], 1);
}

__global__ void dinv_k() {
    int i = blockIdx.x * blockDim.x + threadIdx.x;
    if (i < NN) g_dinv[i] = rsqrtf((float)g_counts[i] + 1.0f);
}

// Block-level inclusive scan -> exclusive per-element + block sums
__global__ void scan1_k() {
    __shared__ int sh[1024];
    int i = blockIdx.x * 1024 + threadIdx.x;
    int v = (i < NN) ? g_counts[i] : 0;
    sh[threadIdx.x] = v;
    __syncthreads();
    #pragma unroll
    for (int o = 1; o < 1024; o <<= 1) {
        int t = (threadIdx.x >= o) ? sh[threadIdx.x - o] : 0;
        __syncthreads();
        sh[threadIdx.x] += t;
        __syncthreads();
    }
    if (i < NN) g_off[i] = sh[threadIdx.x] - v;   // exclusive within block
    if (threadIdx.x == 1023) g_bsums[blockIdx.x] = sh[1023];
}

__global__ void scan2_k(int nb) {
    __shared__ int sh[128];
    int t = threadIdx.x;
    int v = (t < nb) ? g_bsums[t] : 0;
    sh[t] = v;
    __syncthreads();
    #pragma unroll
    for (int o = 1; o < 128; o <<= 1) {
        int tv = (t >= o) ? sh[t - o] : 0;
        __syncthreads();
        sh[t] += tv;
        __syncthreads();
    }
    if (t < nb) g_bsums[t] = sh[t] - v;           // exclusive block offsets
}

__global__ void scan3_k() {
    int i = blockIdx.x * 1024 + threadIdx.x;
    if (i < NN) {
        int v = g_off[i] + g_bsums[blockIdx.x];
        g_off[i] = v;
        g_cursor[i] = v;
    }
    if (i == 0) g_off[NN] = EE;
}

__global__ void scatter_k(const int* __restrict__ rowp,
                          const int* __restrict__ colp) {
    int i = blockIdx.x * blockDim.x + threadIdx.x;
    int stride = gridDim.x * blockDim.x;
    for (; i < EE; i += stride) {
        int r = rowp[i];
        int c = colp[i];
        float w = g_dinv[r] * g_dinv[c];
        int p = atomicAdd(&g_cursor[c], 1);
        g_src[p] = r;
        g_wt[p]  = w;
    }
}

// ---------------- GEMM: C[M,128] = A[M,128] @ W[128,128] (+bias) ----------------
// 64 rows/block, 256 threads, each thread computes 4x8 outputs. K tiled by 32.
__global__ void gemm_k(const float* __restrict__ A, const float* __restrict__ W,
                       const float* __restrict__ bias, float* __restrict__ C, int M) {
    __shared__ float Ws[32][128];
    __shared__ float Xs[32][68];   // transposed A tile, padded
    int tid = threadIdx.x;
    int tx = tid & 15;       // 16 col groups x 8 cols
    int ty = tid >> 4;       // 16 row groups x 4 rows
    int row0 = blockIdx.x * 64;

    float acc[4][8];
    #pragma unroll
    for (int r = 0; r < 4; r++)
        #pragma unroll
        for (int c = 0; c < 8; c++) acc[r][c] = 0.0f;

    for (int kc = 0; kc < 128; kc += 32) {
        // load W chunk [32,128]
        #pragma unroll
        for (int i = 0; i < 4; i++) {
            int idx = tid + i * 256;          // 0..1023
            int k = idx >> 5, c4 = idx & 31;
            *(float4*)&Ws[k][c4 * 4] = *(const float4*)&W[(kc + k) * 128 + c4 * 4];
        }
        // load A chunk [64,32] transposed
        #pragma unroll
        for (int i = 0; i < 2; i++) {
            int idx = tid + i * 256;          // 0..511
            int r = idx >> 3, kg = idx & 7;
            int grow = row0 + r;
            float4 v = make_float4(0.f, 0.f, 0.f, 0.f);
            if (grow < M) v = *(const float4*)&A[(size_t)grow * 128 + kc + kg * 4];
            Xs[kg * 4 + 0][r] = v.x;
            Xs[kg * 4 + 1][r] = v.y;
            Xs[kg * 4 + 2][r] = v.z;
            Xs[kg * 4 + 3][r] = v.w;
        }
        __syncthreads();
        #pragma unroll 8
        for (int k = 0; k < 32; k++) {
            float4 a  = *(const float4*)&Xs[k][ty * 4];
            float4 b0 = *(const float4*)&Ws[k][tx * 8];
            float4 b1 = *(const float4*)&Ws[k][tx * 8 + 4];
            float av[4] = {a.x, a.y, a.z, a.w};
            float bv[8] = {b0.x, b0.y, b0.z, b0.w, b1.x, b1.y, b1.z, b1.w};
            #pragma unroll
            for (int r = 0; r < 4; r++)
                #pragma unroll
                for (int c = 0; c < 8; c++) acc[r][c] += av[r] * bv[c];
        }
        __syncthreads();
    }

    int col0 = tx * 8;
    float bb[8];
    #pragma unroll
    for (int c = 0; c < 8; c++) bb[c] = bias ? bias[col0 + c] : 0.0f;
    #pragma unroll
    for (int r = 0; r < 4; r++) {
        int grow = row0 + ty * 4 + r;
        if (grow < M) {
            float4 o0 = make_float4(acc[r][0] + bb[0], acc[r][1] + bb[1],
                                    acc[r][2] + bb[2], acc[r][3] + bb[3]);
            float4 o1 = make_float4(acc[r][4] + bb[4], acc[r][5] + bb[5],
                                    acc[r][6] + bb[6], acc[r][7] + bb[7]);
            *(float4*)&C[(size_t)grow * 128 + col0]     = o0;
            *(float4*)&C[(size_t)grow * 128 + col0 + 4] = o1;
        }
    }
}

// ---------------- aggregation: out = A h (normalized adj incl self loop) + bias --
// one block (128 threads) per node; thread t owns feature column t
__global__ void agg_k(const float* __restrict__ h, const float* __restrict__ bias,
                      float* __restrict__ out) {
    int n = blockIdx.x;
    int t = threadIdx.x;
    float di = g_dinv[n];
    float acc = h[(size_t)n * DD + t] * di * di + bias[t];
    int j = g_off[n], e = g_off[n + 1];
    for (; j + 4 <= e; j += 4) {
        int   s0 = g_src[j],   s1 = g_src[j + 1], s2 = g_src[j + 2], s3 = g_src[j + 3];
        float w0 = g_wt[j],    w1 = g_wt[j + 1],  w2 = g_wt[j + 2],  w3 = g_wt[j + 3];
        float v0 = h[(size_t)s0 * DD + t];
        float v1 = h[(size_t)s1 * DD + t];
        float v2 = h[(size_t)s2 * DD + t];
        float v3 = h[(size_t)s3 * DD + t];
        acc += v0 * w0; acc += v1 * w1; acc += v2 * w2; acc += v3 * w3;
    }
    for (; j < e; ++j) acc += h[(size_t)g_src[j] * DD + t] * g_wt[j];
    out[(size_t)n * DD + t] = acc;
}

// ---------------- BatchNorm ----------------
__global__ void bnstats_k(const float* __restrict__ x) {
    int t = threadIdx.x;
    float s = 0.0f, q = 0.0f;
    for (int r = blockIdx.x; r < NN; r += gridDim.x) {
        float v = x[(size_t)r * DD + t];
        s += v; q += v * v;
    }
    atomicAdd(&g_colsum[t], s);
    atomicAdd(&g_colsq[t], q);
}

__global__ void bnprep_k(const float* __restrict__ g, const float* __restrict__ be) {
    int t = threadIdx.x;
    float mu  = g_colsum[t] * (1.0f / NN);
    float var = g_colsq[t] * (1.0f / NN) - mu * mu;
    float sc  = g[t] * rsqrtf(var + 1e-5f);
    g_scale[t] = sc;
    g_shift[t] = be[t] - mu * sc;
}

// out = relu(x*scale+shift) + res
__global__ void bnapply_k(const float* __restrict__ x, const float* __restrict__ res,
                          float* __restrict__ out) {
    size_t i = (size_t)blockIdx.x * blockDim.x + threadIdx.x;
    size_t stride = (size_t)gridDim.x * blockDim.x;
    size_t total = (size_t)NN * DD;
    for (; i < total; i += stride) {
        int c = (int)(i & 127);
        out[i] = fmaxf(fmaf(x[i], g_scale[c], g_shift[c]), 0.0f) + res[i];
    }
}

// ---------------- LayerNorm over rows: out = LN(h + att) ----------------
__global__ void ln_k(const float* __restrict__ h, const float* __restrict__ att,
                     const float* __restrict__ g, const float* __restrict__ b,
                     float* __restrict__ out) {
    int n = blockIdx.x;
    int t = threadIdx.x;
    size_t idx = (size_t)n * DD + t;
    float v = h[idx] + att[idx];
    float s = v, q = v * v;
    #pragma unroll
    for (int o = 16; o > 0; o >>= 1) {
        s += __shfl_xor_sync(0xFFFFFFFFu, s, o);
        q += __shfl_xor_sync(0xFFFFFFFFu, q, o);
    }
    __shared__ float ss[4], qq[4];
    if ((t & 31) == 0) { ss[t >> 5] = s; qq[t >> 5] = q; }
    __syncthreads();
    s = ss[0] + ss[1] + ss[2] + ss[3];
    q = qq[0] + qq[1] + qq[2] + qq[3];
    float mu  = s * (1.0f / 128.0f);
    float var = q * (1.0f / 128.0f) - mu * mu;
    out[idx] = (v - mu) * rsqrtf(var + 1e-5f) * g[t] + b[t];
}

// ---------------- launch ----------------
extern "C" void kernel_launch(void* const* d_in, const int* in_sizes, int n_in,
                              void* d_out, int out_size) {
    const float* x  = (const float*)d_in[0];
    const int*   ei = (const int*)d_in[1];   // int32: JAX default x64-disabled downcasts int64
    const float* W0 = (const float*)d_in[2];  const float* b0 = (const float*)d_in[3];
    const float* W1 = (const float*)d_in[4];  const float* b1 = (const float*)d_in[5];
    const float* W2 = (const float*)d_in[6];  const float* b2 = (const float*)d_in[7];
    const float* g0 = (const float*)d_in[8];  const float* be0 = (const float*)d_in[9];
    const float* g1 = (const float*)d_in[10]; const float* be1 = (const float*)d_in[11];
    const float* Wv = (const float*)d_in[12]; const float* bv = (const float*)d_in[13];
    const float* Wo = (const float*)d_in[14]; const float* bo = (const float*)d_in[15];
    const float* lng = (const float*)d_in[16]; const float* lnb = (const float*)d_in[17];
    float* out = (float*)d_out;

    void *pA, *pB, *pC;
    cudaGetSymbolAddress(&pA, g_bufA);
    cudaGetSymbolAddress(&pB, g_bufB);
    cudaGetSymbolAddress(&pC, g_bufC);
    float* A = (float*)pA;
    float* B = (float*)pB;
    float* C = (float*)pC;

    const int* rowp = ei;
    const int* colp = ei + EE;

    const int SCAN_BLOCKS = (NN + 1023) / 1024;  // 98
    const int GEMM_BLOCKS = (NN + 63) / 64;      // 1563

    // --- build normalized-adjacency CSR (by destination) ---
    zero_counts_k<<<(NN + 255) / 256, 256>>>();
    hist_k<<<2048, 256>>>(colp);
    dinv_k<<<(NN + 255) / 256, 256>>>();
    scan1_k<<<SCAN_BLOCKS, 1024>>>();
    scan2_k<<<1, 128>>>(SCAN_BLOCKS);
    scan3_k<<<SCAN_BLOCKS, 1024>>>();
    scatter_k<<<2048, 256>>>(rowp, colp);

    // --- layer 0: conv -> BN -> relu -> +x ---
    gemm_k<<<GEMM_BLOCKS, 256>>>(x, W0, nullptr, A, NN);     // A = x @ W0
    agg_k<<<NN, 128>>>(A, b0, B);                            // B = conv0 out
    zero_stats_k<<<1, 128>>>();
    bnstats_k<<<512, 128>>>(B);
    bnprep_k<<<1, 128>>>(g0, be0);
    bnapply_k<<<4096, 256>>>(B, x, C);                       // C = layer0 out

    // --- layer 1 ---
    gemm_k<<<GEMM_BLOCKS, 256>>>(C, W1, nullptr, A, NN);     // A = C @ W1
    agg_k<<<NN, 128>>>(A, b1, B);                            // B = conv1 out
    zero_stats_k<<<1, 128>>>();
    bnstats_k<<<512, 128>>>(B);
    bnprep_k<<<1, 128>>>(g1, be1);
    bnapply_k<<<4096, 256>>>(B, C, A);                       // A = layer1 out (h)

    // --- MHA (seq_len=1) + LayerNorm ---
    gemm_k<<<GEMM_BLOCKS, 256>>>(A, Wv, bv, B, NN);          // B = h@Wv + bv
    gemm_k<<<GEMM_BLOCKS, 256>>>(B, Wo, bo, C, NN);          // C = att
    ln_k<<<NN, 128>>>(A, C, lng, lnb, B);                    // B = LN(h + att)

    // --- output conv ---
    gemm_k<<<GEMM_BLOCKS, 256>>>(B, W2, nullptr, C, NN);     // C = B @ W2
    agg_k<<<NN, 128>>>(C, b2, out);                          // out = conv2
}

// round 8
// speedup vs baseline: 1.7231x; 1.7231x over previous
#include <cuda_runtime.h>
#include <cuda_fp16.h>
#include <cuda_bf16.h>
#include <cstdint>

#define NN 100000
#define EE 1600000
#define DD 128

// ---------------- scratch (device globals; no runtime allocation) ----------------
__device__ float g_bufA[(size_t)NN * DD];
__device__ float g_bufB[(size_t)NN * DD];
__device__ float g_bufC[(size_t)NN * DD];
__device__ __half g_h16[(size_t)NN * DD];
__device__ unsigned short g_wth[5 * DD * DD];   // W^T hi (bf16 bits), per matrix
__device__ unsigned short g_wtl[5 * DD * DD];   // W^T lo
__device__ int   g_counts[NN];
__device__ int   g_off[NN + 1];
__device__ int   g_cursor[NN];
__device__ int   g_bsums[128];
__device__ float g_dinv[NN];
__device__ int   g_src[EE];
__device__ float g_wt[EE];
__device__ float g_colsum[DD];
__device__ float g_colsq[DD];
__device__ float g_scale[DD];
__device__ float g_shift[DD];

// ---------------- graph preprocessing ----------------

__global__ void zero_counts_k() {
    int i = blockIdx.x * blockDim.x + threadIdx.x;
    if (i < NN) g_counts[i] = 0;
}

__global__ void zero_stats_k() {
    int t = threadIdx.x;
    if (t < DD) { g_colsum[t] = 0.0f; g_colsq[t] = 0.0f; }
}

__global__ void hist_k(const int* __restrict__ colp) {
    int i = blockIdx.x * blockDim.x + threadIdx.x;
    int stride = gridDim.x * blockDim.x;
    for (; i < EE; i += stride) atomicAdd(&g_counts[colp[i]], 1);
}

__global__ void dinv_k() {
    int i = blockIdx.x * blockDim.x + threadIdx.x;
    if (i < NN) g_dinv[i] = rsqrtf((float)g_counts[i] + 1.0f);
}

__global__ void scan1_k() {
    __shared__ int sh[1024];
    int i = blockIdx.x * 1024 + threadIdx.x;
    int v = (i < NN) ? g_counts[i] : 0;
    sh[threadIdx.x] = v;
    __syncthreads();
    #pragma unroll
    for (int o = 1; o < 1024; o <<= 1) {
        int t = (threadIdx.x >= o) ? sh[threadIdx.x - o] : 0;
        __syncthreads();
        sh[threadIdx.x] += t;
        __syncthreads();
    }
    if (i < NN) g_off[i] = sh[threadIdx.x] - v;
    if (threadIdx.x == 1023) g_bsums[blockIdx.x] = sh[1023];
}

__global__ void scan2_k(int nb) {
    __shared__ int sh[128];
    int t = threadIdx.x;
    int v = (t < nb) ? g_bsums[t] : 0;
    sh[t] = v;
    __syncthreads();
    #pragma unroll
    for (int o = 1; o < 128; o <<= 1) {
        int tv = (t >= o) ? sh[t - o] : 0;
        __syncthreads();
        sh[t] += tv;
        __syncthreads();
    }
    if (t < nb) g_bsums[t] = sh[t] - v;
}

__global__ void scan3_k() {
    int i = blockIdx.x * 1024 + threadIdx.x;
    if (i < NN) {
        int v = g_off[i] + g_bsums[blockIdx.x];
        g_off[i] = v;
        g_cursor[i] = v;
    }
    if (i == 0) g_off[NN] = EE;
}

__global__ void scatter_k(const int* __restrict__ rowp,
                          const int* __restrict__ colp) {
    int i = blockIdx.x * blockDim.x + threadIdx.x;
    int stride = gridDim.x * blockDim.x;
    for (; i < EE; i += stride) {
        int r = rowp[i];
        int c = colp[i];
        float w = g_dinv[r] * g_dinv[c];
        int p = atomicAdd(&g_cursor[c], 1);
        g_src[p] = r;
        g_wt[p]  = w;
    }
}

// ---------------- W split: Wt_hi/lo[n][k] = bf16 split of W[k][n] ----------------
__global__ void wsplit_k(const float* __restrict__ W0, const float* __restrict__ W1,
                         const float* __restrict__ W2, const float* __restrict__ W3,
                         const float* __restrict__ W4) {
    int gidx = blockIdx.x * blockDim.x + threadIdx.x;  // 0 .. 5*16384
    if (gidx >= 5 * DD * DD) return;
    int m = gidx / (DD * DD);
    int idx = gidx - m * (DD * DD);
    const float* W = (m == 0) ? W0 : (m == 1) ? W1 : (m == 2) ? W2 : (m == 3) ? W3 : W4;
    int k = idx >> 7, n = idx & 127;
    float w = W[idx];                       // W[k][n]
    __nv_bfloat16 h = __float2bfloat16_rn(w);
    float hf = __bfloat162float(h);
    __nv_bfloat16 l = __float2bfloat16_rn(w - hf);
    g_wth[m * DD * DD + n * DD + k] = __bfloat16_as_ushort(h);
    g_wtl[m * DD * DD + n * DD + k] = __bfloat16_as_ushort(l);
}

// ---------------- tensor-core GEMM: C[M,128] = A[M,128] @ W[128,128] (+bias) -----
// bf16 hi/lo 3-term emulation; fp32 accumulate. Block = 256 thr = 8 warps,
// warp handles 16 rows x 128 cols. Optional half2 shadow copy for gather table.

__device__ __forceinline__ unsigned pack_bf16x2(float lo_elem, float hi_elem) {
    unsigned r;
    asm("cvt.rn.bf16x2.f32 %0, %1, %2;" : "=r"(r) : "f"(hi_elem), "f"(lo_elem));
    return r;  // low half = lo_elem (element k), high half = hi_elem (element k+1)
}

__device__ __forceinline__ void mma16816(float* c, const unsigned* a,
                                         unsigned b0, unsigned b1) {
    asm volatile(
        "mma.sync.aligned.m16n8k16.row.col.f32.bf16.bf16.f32 "
        "{%0,%1,%2,%3}, {%4,%5,%6,%7}, {%8,%9}, {%0,%1,%2,%3};"
        : "+f"(c[0]), "+f"(c[1]), "+f"(c[2]), "+f"(c[3])
        : "r"(a[0]), "r"(a[1]), "r"(a[2]), "r"(a[3]), "r"(b0), "r"(b1));
}

// split float2 -> (hi bf16x2, lo bf16x2)
__device__ __forceinline__ void split2(float2 x, unsigned& hi, unsigned& lo) {
    hi = pack_bf16x2(x.x, x.y);
    float h0 = __uint_as_float(hi << 16);
    float h1 = __uint_as_float(hi & 0xFFFF0000u);
    lo = pack_bf16x2(x.x - h0, x.y - h1);
}

#define WT_STRIDE 68   // padded row stride in u32 words (136 halves)

__global__ __launch_bounds__(256) void gemm_tc(
    const float* __restrict__ A, const unsigned short* __restrict__ Wthi,
    const unsigned short* __restrict__ Wtlo, const float* __restrict__ bias,
    float* __restrict__ C, __half2* __restrict__ C16, int M)
{
    extern __shared__ unsigned smw[];           // [2][128][68] u32
    unsigned* WhiS = smw;
    unsigned* WloS = smw + DD * WT_STRIDE;

    int tid = threadIdx.x;
    // stage W^T hi/lo into smem with pad
    const unsigned* ghi = (const unsigned*)Wthi;
    const unsigned* glo = (const unsigned*)Wtlo;
    #pragma unroll
    for (int i = tid; i < DD * 64; i += 256) {
        int n = i >> 6, kw = i & 63;
        WhiS[n * WT_STRIDE + kw] = ghi[i];
        WloS[n * WT_STRIDE + kw] = glo[i];
    }
    __syncthreads();

    int warp = tid >> 5, lane = tid & 31;
    int g = lane >> 2, tig = lane & 3;
    int row0 = blockIdx.x * 128 + warp * 16 + g;   // fragment row (a0/a2/c0/c1)
    int row1 = row0 + 8;                           // a1/a3/c2/c3
    bool v0 = row0 < M, v1 = row1 < M;
    const float* ar0 = A + (size_t)row0 * DD;
    const float* ar1 = A + (size_t)row1 * DD;

    float acc[16][4];
    #pragma unroll
    for (int nt = 0; nt < 16; nt++)
        #pragma unroll
        for (int i = 0; i < 4; i++) acc[nt][i] = 0.0f;

    const float2 z2 = make_float2(0.f, 0.f);

    #pragma unroll
    for (int kc = 0; kc < 8; kc++) {
        int k0 = kc * 16 + 2 * tig;
        float2 x0 = v0 ? *(const float2*)(ar0 + k0)     : z2;   // a0
        float2 x1 = v1 ? *(const float2*)(ar1 + k0)     : z2;   // a1
        float2 x2 = v0 ? *(const float2*)(ar0 + k0 + 8) : z2;   // a2
        float2 x3 = v1 ? *(const float2*)(ar1 + k0 + 8) : z2;   // a3
        unsigned ahi[4], alo[4];
        split2(x0, ahi[0], alo[0]);
        split2(x1, ahi[1], alo[1]);
        split2(x2, ahi[2], alo[2]);
        split2(x3, ahi[3], alo[3]);

        int kw = kc * 8 + tig;
        #pragma unroll
        for (int nt = 0; nt < 16; nt++) {
            int nrow = (nt * 8 + g) * WT_STRIDE + kw;
            unsigned bh0 = WhiS[nrow];
            unsigned bh1 = WhiS[nrow + 4];
            unsigned bl0 = WloS[nrow];
            unsigned bl1 = WloS[nrow + 4];
            mma16816(acc[nt], ahi, bh0, bh1);
            mma16816(acc[nt], ahi, bl0, bl1);
            mma16816(acc[nt], alo, bh0, bh1);
        }
    }

    // epilogue
    #pragma unroll
    for (int nt = 0; nt < 16; nt++) {
        int col = nt * 8 + 2 * tig;
        float2 bb = bias ? *(const float2*)(bias + col) : z2;
        float o0 = acc[nt][0] + bb.x, o1 = acc[nt][1] + bb.y;
        float o2 = acc[nt][2] + bb.x, o3 = acc[nt][3] + bb.y;
        if (v0) {
            *(float2*)(C + (size_t)row0 * DD + col) = make_float2(o0, o1);
            if (C16) C16[(size_t)row0 * 64 + (col >> 1)] = __floats2half2_rn(o0, o1);
        }
        if (v1) {
            *(float2*)(C + (size_t)row1 * DD + col) = make_float2(o2, o3);
            if (C16) C16[(size_t)row1 * 64 + (col >> 1)] = __floats2half2_rn(o2, o3);
        }
    }
}

// ---------------- aggregation: out = A_hat h + bias -----------------------------
// 4 nodes per 256-thread block; 64 threads per node, thread t owns cols {2t,2t+1}.
// Gathers from the fp16 shadow table; self term from fp32.
__global__ __launch_bounds__(256) void agg_k(
    const float* __restrict__ h32, const __half2* __restrict__ h16,
    const float* __restrict__ bias, float* __restrict__ out)
{
    int n = blockIdx.x * 4 + (threadIdx.x >> 6);
    if (n >= NN) return;
    int t = threadIdx.x & 63;

    float di = g_dinv[n];
    float dii = di * di;
    float2 self = *(const float2*)(h32 + (size_t)n * DD + 2 * t);
    float2 bb   = *(const float2*)(bias + 2 * t);
    float ax = fmaf(self.x, dii, bb.x);
    float ay = fmaf(self.y, dii, bb.y);

    int j = g_off[n], e = g_off[n + 1];
    for (; j + 4 <= e; j += 4) {
        int   s0 = g_src[j],     s1 = g_src[j + 1];
        int   s2 = g_src[j + 2], s3 = g_src[j + 3];
        float w0 = g_wt[j],      w1 = g_wt[j + 1];
        float w2 = g_wt[j + 2],  w3 = g_wt[j + 3];
        float2 f0 = __half22float2(h16[(size_t)s0 * 64 + t]);
        float2 f1 = __half22float2(h16[(size_t)s1 * 64 + t]);
        float2 f2 = __half22float2(h16[(size_t)s2 * 64 + t]);
        float2 f3 = __half22float2(h16[(size_t)s3 * 64 + t]);
        ax = fmaf(f0.x, w0, ax); ay = fmaf(f0.y, w0, ay);
        ax = fmaf(f1.x, w1, ax); ay = fmaf(f1.y, w1, ay);
        ax = fmaf(f2.x, w2, ax); ay = fmaf(f2.y, w2, ay);
        ax = fmaf(f3.x, w3, ax); ay = fmaf(f3.y, w3, ay);
    }
    for (; j < e; ++j) {
        float w = g_wt[j];
        float2 f = __half22float2(h16[(size_t)g_src[j] * 64 + t]);
        ax = fmaf(f.x, w, ax); ay = fmaf(f.y, w, ay);
    }
    *(float2*)(out + (size_t)n * DD + 2 * t) = make_float2(ax, ay);
}

// ---------------- BatchNorm ----------------
__global__ void bnstats_k(const float* __restrict__ x) {
    int t = threadIdx.x;
    float s = 0.0f, q = 0.0f;
    for (int r = blockIdx.x; r < NN; r += gridDim.x) {
        float v = x[(size_t)r * DD + t];
        s += v; q += v * v;
    }
    atomicAdd(&g_colsum[t], s);
    atomicAdd(&g_colsq[t], q);
}

__global__ void bnprep_k(const float* __restrict__ g, const float* __restrict__ be) {
    int t = threadIdx.x;
    float mu  = g_colsum[t] * (1.0f / NN);
    float var = g_colsq[t] * (1.0f / NN) - mu * mu;
    float sc  = g[t] * rsqrtf(var + 1e-5f);
    g_scale[t] = sc;
    g_shift[t] = be[t] - mu * sc;
}

// out = relu(x*scale+shift) + res
__global__ void bnapply_k(const float* __restrict__ x, const float* __restrict__ res,
                          float* __restrict__ out) {
    size_t i = (size_t)blockIdx.x * blockDim.x + threadIdx.x;
    size_t stride = (size_t)gridDim.x * blockDim.x;
    size_t total = (size_t)NN * DD;
    for (; i < total; i += stride) {
        int c = (int)(i & 127);
        out[i] = fmaxf(fmaf(x[i], g_scale[c], g_shift[c]), 0.0f) + res[i];
    }
}

// ---------------- LayerNorm over rows: out = LN(h + att) ----------------
__global__ void ln_k(const float* __restrict__ h, const float* __restrict__ att,
                     const float* __restrict__ g, const float* __restrict__ b,
                     float* __restrict__ out) {
    int n = blockIdx.x;
    int t = threadIdx.x;
    size_t idx = (size_t)n * DD + t;
    float v = h[idx] + att[idx];
    float s = v, q = v * v;
    #pragma unroll
    for (int o = 16; o > 0; o >>= 1) {
        s += __shfl_xor_sync(0xFFFFFFFFu, s, o);
        q += __shfl_xor_sync(0xFFFFFFFFu, q, o);
    }
    __shared__ float ss[4], qq[4];
    if ((t & 31) == 0) { ss[t >> 5] = s; qq[t >> 5] = q; }
    __syncthreads();
    s = ss[0] + ss[1] + ss[2] + ss[3];
    q = qq[0] + qq[1] + qq[2] + qq[3];
    float mu  = s * (1.0f / 128.0f);
    float var = q * (1.0f / 128.0f) - mu * mu;
    out[idx] = (v - mu) * rsqrtf(var + 1e-5f) * g[t] + b[t];
}

// ---------------- launch ----------------
extern "C" void kernel_launch(void* const* d_in, const int* in_sizes, int n_in,
                              void* d_out, int out_size) {
    const float* x  = (const float*)d_in[0];
    const int*   ei = (const int*)d_in[1];   // int32 (JAX x64-disabled)
    const float* W0 = (const float*)d_in[2];  const float* b0 = (const float*)d_in[3];
    const float* W1 = (const float*)d_in[4];  const float* b1 = (const float*)d_in[5];
    const float* W2 = (const float*)d_in[6];  const float* b2 = (const float*)d_in[7];
    const float* g0 = (const float*)d_in[8];  const float* be0 = (const float*)d_in[9];
    const float* g1 = (const float*)d_in[10]; const float* be1 = (const float*)d_in[11];
    const float* Wv = (const float*)d_in[12]; const float* bv = (const float*)d_in[13];
    const float* Wo = (const float*)d_in[14]; const float* bo = (const float*)d_in[15];
    const float* lng = (const float*)d_in[16]; const float* lnb = (const float*)d_in[17];
    float* out = (float*)d_out;

    void *pA, *pB, *pC, *pH, *pWh, *pWl;
    cudaGetSymbolAddress(&pA, g_bufA);
    cudaGetSymbolAddress(&pB, g_bufB);
    cudaGetSymbolAddress(&pC, g_bufC);
    cudaGetSymbolAddress(&pH, g_h16);
    cudaGetSymbolAddress(&pWh, g_wth);
    cudaGetSymbolAddress(&pWl, g_wtl);
    float* A = (float*)pA;
    float* B = (float*)pB;
    float* C = (float*)pC;
    __half2* H16 = (__half2*)pH;
    const unsigned short* Wh = (const unsigned short*)pWh;
    const unsigned short* Wl = (const unsigned short*)pWl;

    const int* rowp = ei;
    const int* colp = ei + EE;

    const int SCAN_BLOCKS = (NN + 1023) / 1024;   // 98
    const int GEMM_BLOCKS = (NN + 127) / 128;     // 782
    const int AGG_BLOCKS  = (NN + 3) / 4;         // 25000
    const int SMEM_W = 2 * DD * WT_STRIDE * 4;    // 69632 B

    static int smem_set = 0;
    if (!smem_set) {
        cudaFuncSetAttribute(gemm_tc, cudaFuncAttributeMaxDynamicSharedMemorySize, SMEM_W);
        smem_set = 1;
    }

    // --- build normalized-adjacency CSR (by destination) + W splits ---
    zero_counts_k<<<(NN + 255) / 256, 256>>>();
    hist_k<<<2048, 256>>>(colp);
    dinv_k<<<(NN + 255) / 256, 256>>>();
    scan1_k<<<SCAN_BLOCKS, 1024>>>();
    scan2_k<<<1, 128>>>(SCAN_BLOCKS);
    scan3_k<<<SCAN_BLOCKS, 1024>>>();
    scatter_k<<<2048, 256>>>(rowp, colp);
    wsplit_k<<<(5 * DD * DD + 255) / 256, 256>>>(W0, W1, W2, Wv, Wo);

    const unsigned short* Wh0 = Wh;               const unsigned short* Wl0 = Wl;
    const unsigned short* Wh1 = Wh + 1 * DD * DD; const unsigned short* Wl1 = Wl + 1 * DD * DD;
    const unsigned short* Wh2 = Wh + 2 * DD * DD; const unsigned short* Wl2 = Wl + 2 * DD * DD;
    const unsigned short* Whv = Wh + 3 * DD * DD; const unsigned short* Wlv = Wl + 3 * DD * DD;
    const unsigned short* Who = Wh + 4 * DD * DD; const unsigned short* Wlo_ = Wl + 4 * DD * DD;

    // --- layer 0: conv -> BN -> relu -> +x ---
    gemm_tc<<<GEMM_BLOCKS, 256, SMEM_W>>>(x, Wh0, Wl0, nullptr, A, H16, NN);  // A = x@W0 (+h16)
    agg_k<<<AGG_BLOCKS, 256>>>(A, H16, b0, B);                                // B = conv0
    zero_stats_k<<<1, 128>>>();
    bnstats_k<<<512, 128>>>(B);
    bnprep_k<<<1, 128>>>(g0, be0);
    bnapply_k<<<4096, 256>>>(B, x, C);                                        // C = layer0 out

    // --- layer 1 ---
    gemm_tc<<<GEMM_BLOCKS, 256, SMEM_W>>>(C, Wh1, Wl1, nullptr, A, H16, NN);  // A = C@W1
    agg_k<<<AGG_BLOCKS, 256>>>(A, H16, b1, B);                                // B = conv1
    zero_stats_k<<<1, 128>>>();
    bnstats_k<<<512, 128>>>(B);
    bnprep_k<<<1, 128>>>(g1, be1);
    bnapply_k<<<4096, 256>>>(B, C, A);                                        // A = layer1 out (h)

    // --- MHA (seq_len=1) + LayerNorm ---
    gemm_tc<<<GEMM_BLOCKS, 256, SMEM_W>>>(A, Whv, Wlv, bv, B, nullptr, NN);   // B = h@Wv+bv
    gemm_tc<<<GEMM_BLOCKS, 256, SMEM_W>>>(B, Who, Wlo_, bo, C, nullptr, NN);  // C = att
    ln_k<<<NN, 128>>>(A, C, lng, lnb, B);                                     // B = LN(h+att)

    // --- output conv ---
    gemm_tc<<<GEMM_BLOCKS, 256, SMEM_W>>>(B, Wh2, Wl2, nullptr, C, H16, NN);  // C = B@W2
    agg_k<<<AGG_BLOCKS, 256>>>(C, H16, b2, out);                              // out = conv2
}

// round 9
// speedup vs baseline: 2.2010x; 1.2774x over previous
#include <cuda_runtime.h>
#include <cuda_fp16.h>
#include <cuda_bf16.h>
#include <cstdint>

#define NN 100000
#define EE 1600000
#define DD 128

// ---------------- scratch (device globals; no runtime allocation) ----------------
__device__ float g_bufA[(size_t)NN * DD];
__device__ float g_bufB[(size_t)NN * DD];
__device__ float g_bufC[(size_t)NN * DD];
__device__ uint2 g_h16[(size_t)NN * 32];        // fp16 shadow table (row = 32 uint2)
__device__ unsigned short g_wth[4 * DD * DD];   // W^T hi (bf16 bits): W0,W1,W2,Wvo
__device__ unsigned short g_wtl[4 * DD * DD];   // W^T lo
__device__ float g_bvo[DD];
__device__ int   g_counts[NN];
__device__ int   g_off[NN + 1];
__device__ int   g_cursor[NN];
__device__ int   g_bsums[128];
__device__ float g_dinv[NN];
__device__ int   g_src[EE];
__device__ float g_wt[EE];
__device__ float g_psum[512 * DD];
__device__ float g_psq[512 * DD];
__device__ float g_scale[DD];
__device__ float g_shift[DD];

// ---------------- graph preprocessing ----------------

__global__ void zero_counts_k() {
    int i = blockIdx.x * blockDim.x + threadIdx.x;
    if (i < NN) g_counts[i] = 0;
}

__global__ void hist_k(const int* __restrict__ colp) {
    int i = blockIdx.x * blockDim.x + threadIdx.x;
    int stride = gridDim.x * blockDim.x;
    for (; i < EE; i += stride) atomicAdd(&g_counts[colp[i]], 1);
}

// block scan (+ dinv fused)
__global__ void scan1_k() {
    __shared__ int sh[1024];
    int i = blockIdx.x * 1024 + threadIdx.x;
    int v = (i < NN) ? g_counts[i] : 0;
    if (i < NN) g_dinv[i] = rsqrtf((float)v + 1.0f);
    sh[threadIdx.x] = v;
    __syncthreads();
    #pragma unroll
    for (int o = 1; o < 1024; o <<= 1) {
        int t = (threadIdx.x >= o) ? sh[threadIdx.x - o] : 0;
        __syncthreads();
        sh[threadIdx.x] += t;
        __syncthreads();
    }
    if (i < NN) g_off[i] = sh[threadIdx.x] - v;
    if (threadIdx.x == 1023) g_bsums[blockIdx.x] = sh[1023];
}

__global__ void scan2_k(int nb) {
    __shared__ int sh[128];
    int t = threadIdx.x;
    int v = (t < nb) ? g_bsums[t] : 0;
    sh[t] = v;
    __syncthreads();
    #pragma unroll
    for (int o = 1; o < 128; o <<= 1) {
        int tv = (t >= o) ? sh[t - o] : 0;
        __syncthreads();
        sh[t] += tv;
        __syncthreads();
    }
    if (t < nb) g_bsums[t] = sh[t] - v;
}

__global__ void scan3_k() {
    int i = blockIdx.x * 1024 + threadIdx.x;
    if (i < NN) {
        int v = g_off[i] + g_bsums[blockIdx.x];
        g_off[i] = v;
        g_cursor[i] = v;
    }
    if (i == 0) g_off[NN] = EE;
}

__global__ void scatter_k(const int* __restrict__ rowp,
                          const int* __restrict__ colp) {
    int i = blockIdx.x * blockDim.x + threadIdx.x;
    int stride = gridDim.x * blockDim.x;
    for (; i < EE; i += stride) {
        int r = rowp[i];
        int c = colp[i];
        float w = g_dinv[r] * g_dinv[c];
        int p = atomicAdd(&g_cursor[c], 1);
        g_src[p] = r;
        g_wt[p]  = w;
    }
}

// ---------------- W split: slots 0,1,2 = W0,W1,W2 transposed hi/lo ---------------
__global__ void wsplit_k(const float* __restrict__ W0, const float* __restrict__ W1,
                         const float* __restrict__ W2) {
    int gidx = blockIdx.x * blockDim.x + threadIdx.x;
    if (gidx >= 3 * DD * DD) return;
    int m = gidx / (DD * DD);
    int idx = gidx - m * (DD * DD);
    const float* W = (m == 0) ? W0 : (m == 1) ? W1 : W2;
    int k = idx >> 7, n = idx & 127;
    float w = W[idx];
    __nv_bfloat16 h = __float2bfloat16_rn(w);
    float hf = __bfloat162float(h);
    __nv_bfloat16 l = __float2bfloat16_rn(w - hf);
    g_wth[m * DD * DD + n * DD + k] = __bfloat16_as_ushort(h);
    g_wtl[m * DD * DD + n * DD + k] = __bfloat16_as_ushort(l);
}

// ---------------- Wvo = Wv @ Wo (slot 3), bvo = bv @ Wo + bo ---------------------
__global__ void wvo_k(const float* __restrict__ Wv, const float* __restrict__ bv,
                      const float* __restrict__ Wo, const float* __restrict__ bo) {
    __shared__ float rowv[128];
    int t = threadIdx.x;
    if (blockIdx.x < 128) {
        int i = blockIdx.x;
        rowv[t] = Wv[i * 128 + t];
        __syncthreads();
        float s = 0.0f;
        #pragma unroll 8
        for (int k = 0; k < 128; k++) s += rowv[k] * Wo[k * 128 + t];
        __nv_bfloat16 h = __float2bfloat16_rn(s);
        float hf = __bfloat162float(h);
        __nv_bfloat16 l = __float2bfloat16_rn(s - hf);
        g_wth[3 * DD * DD + t * DD + i] = __bfloat16_as_ushort(h);
        g_wtl[3 * DD * DD + t * DD + i] = __bfloat16_as_ushort(l);
    } else {
        float s = bo[t];
        #pragma unroll 8
        for (int k = 0; k < 128; k++) s += bv[k] * Wo[k * 128 + t];
        g_bvo[t] = s;
    }
}

// ---------------- tensor-core GEMM (fused prologue/epilogue variants) ------------
// C[M,128] = f(Ain)[M,128] @ W (+bias).
//  - Res != null : a = relu(Ain*scale+shift) + Res  (BN apply), stored to Store.
//  - lng != null : LayerNorm epilogue: C = LN(Store + acc + bias) per row.
//  - C16 != null : also write half2 shadow copy of plain epilogue output.

__device__ __forceinline__ unsigned pack_bf16x2(float lo_elem, float hi_elem) {
    unsigned r;
    asm("cvt.rn.bf16x2.f32 %0, %1, %2;" : "=r"(r) : "f"(hi_elem), "f"(lo_elem));
    return r;
}

__device__ __forceinline__ void mma16816(float* c, const unsigned* a,
                                         unsigned b0, unsigned b1) {
    asm volatile(
        "mma.sync.aligned.m16n8k16.row.col.f32.bf16.bf16.f32 "
        "{%0,%1,%2,%3}, {%4,%5,%6,%7}, {%8,%9}, {%0,%1,%2,%3};"
        : "+f"(c[0]), "+f"(c[1]), "+f"(c[2]), "+f"(c[3])
        : "r"(a[0]), "r"(a[1]), "r"(a[2]), "r"(a[3]), "r"(b0), "r"(b1));
}

__device__ __forceinline__ void split2(float2 x, unsigned& hi, unsigned& lo) {
    hi = pack_bf16x2(x.x, x.y);
    float h0 = __uint_as_float(hi << 16);
    float h1 = __uint_as_float(hi & 0xFFFF0000u);
    lo = pack_bf16x2(x.x - h0, x.y - h1);
}

#define WT_STRIDE 68

__global__ __launch_bounds__(256) void gemm_tc(
    const float* __restrict__ Ain, const float* __restrict__ Res,
    float* __restrict__ Store,
    const unsigned short* __restrict__ Wthi, const unsigned short* __restrict__ Wtlo,
    const float* __restrict__ bias,
    const float* __restrict__ lng, const float* __restrict__ lnb,
    float* __restrict__ C, __half2* __restrict__ C16, int M)
{
    extern __shared__ unsigned smw[];
    unsigned* WhiS = smw;
    unsigned* WloS = smw + DD * WT_STRIDE;
    float* sSc = (float*)(smw + 2 * DD * WT_STRIDE);
    float* sSh = sSc + DD;

    int tid = threadIdx.x;
    const unsigned* ghi = (const unsigned*)Wthi;
    const unsigned* glo = (const unsigned*)Wtlo;
    #pragma unroll
    for (int i = tid; i < DD * 64; i += 256) {
        int n = i >> 6, kw = i & 63;
        WhiS[n * WT_STRIDE + kw] = ghi[i];
        WloS[n * WT_STRIDE + kw] = glo[i];
    }
    if (Res && tid < 128) { sSc[tid] = g_scale[tid]; sSh[tid] = g_shift[tid]; }
    __syncthreads();

    int warp = tid >> 5, lane = tid & 31;
    int g = lane >> 2, tig = lane & 3;
    int row0 = blockIdx.x * 128 + warp * 16 + g;
    int row1 = row0 + 8;
    bool v0 = row0 < M, v1 = row1 < M;
    const float* ar0 = Ain + (size_t)row0 * DD;
    const float* ar1 = Ain + (size_t)row1 * DD;

    float acc[16][4];
    #pragma unroll
    for (int nt = 0; nt < 16; nt++)
        #pragma unroll
        for (int i = 0; i < 4; i++) acc[nt][i] = 0.0f;

    const float2 z2 = make_float2(0.f, 0.f);

    #pragma unroll
    for (int kc = 0; kc < 8; kc++) {
        int k0 = kc * 16 + 2 * tig;
        float2 x0 = v0 ? *(const float2*)(ar0 + k0)     : z2;
        float2 x1 = v1 ? *(const float2*)(ar1 + k0)     : z2;
        float2 x2 = v0 ? *(const float2*)(ar0 + k0 + 8) : z2;
        float2 x3 = v1 ? *(const float2*)(ar1 + k0 + 8) : z2;

        if (Res) {
            float2 scA = make_float2(sSc[k0], sSc[k0 + 1]);
            float2 shA = make_float2(sSh[k0], sSh[k0 + 1]);
            float2 scB = make_float2(sSc[k0 + 8], sSc[k0 + 9]);
            float2 shB = make_float2(sSh[k0 + 8], sSh[k0 + 9]);
            float2 r0 = v0 ? *(const float2*)(Res + (size_t)row0 * DD + k0)     : z2;
            float2 r1 = v1 ? *(const float2*)(Res + (size_t)row1 * DD + k0)     : z2;
            float2 r2 = v0 ? *(const float2*)(Res + (size_t)row0 * DD + k0 + 8) : z2;
            float2 r3 = v1 ? *(const float2*)(Res + (size_t)row1 * DD + k0 + 8) : z2;
            x0.x = fmaxf(fmaf(x0.x, scA.x, shA.x), 0.f) + r0.x;
            x0.y = fmaxf(fmaf(x0.y, scA.y, shA.y), 0.f) + r0.y;
            x1.x = fmaxf(fmaf(x1.x, scA.x, shA.x), 0.f) + r1.x;
            x1.y = fmaxf(fmaf(x1.y, scA.y, shA.y), 0.f) + r1.y;
            x2.x = fmaxf(fmaf(x2.x, scB.x, shB.x), 0.f) + r2.x;
            x2.y = fmaxf(fmaf(x2.y, scB.y, shB.y), 0.f) + r2.y;
            x3.x = fmaxf(fmaf(x3.x, scB.x, shB.x), 0.f) + r3.x;
            x3.y = fmaxf(fmaf(x3.y, scB.y, shB.y), 0.f) + r3.y;
            if (v0) {
                *(float2*)(Store + (size_t)row0 * DD + k0)     = x0;
                *(float2*)(Store + (size_t)row0 * DD + k0 + 8) = x2;
            }
            if (v1) {
                *(float2*)(Store + (size_t)row1 * DD + k0)     = x1;
                *(float2*)(Store + (size_t)row1 * DD + k0 + 8) = x3;
            }
        }

        unsigned ahi[4], alo[4];
        split2(x0, ahi[0], alo[0]);
        split2(x1, ahi[1], alo[1]);
        split2(x2, ahi[2], alo[2]);
        split2(x3, ahi[3], alo[3]);

        int kw = kc * 8 + tig;
        #pragma unroll
        for (int nt = 0; nt < 16; nt++) {
            int nrow = (nt * 8 + g) * WT_STRIDE + kw;
            unsigned bh0 = WhiS[nrow];
            unsigned bh1 = WhiS[nrow + 4];
            unsigned bl0 = WloS[nrow];
            unsigned bl1 = WloS[nrow + 4];
            mma16816(acc[nt], ahi, bh0, bh1);
            mma16816(acc[nt], ahi, bl0, bl1);
            mma16816(acc[nt], alo, bh0, bh1);
        }
    }

    if (!lng) {
        // plain epilogue
        #pragma unroll
        for (int nt = 0; nt < 16; nt++) {
            int col = nt * 8 + 2 * tig;
            float2 bb = bias ? *(const float2*)(bias + col) : z2;
            float o0 = acc[nt][0] + bb.x, o1 = acc[nt][1] + bb.y;
            float o2 = acc[nt][2] + bb.x, o3 = acc[nt][3] + bb.y;
            if (v0) {
                *(float2*)(C + (size_t)row0 * DD + col) = make_float2(o0, o1);
                if (C16) C16[(size_t)row0 * 64 + (col >> 1)] = __floats2half2_rn(o0, o1);
            }
            if (v1) {
                *(float2*)(C + (size_t)row1 * DD + col) = make_float2(o2, o3);
                if (C16) C16[(size_t)row1 * 64 + (col >> 1)] = __floats2half2_rn(o2, o3);
            }
        }
    } else {
        // LayerNorm epilogue: v = Store(row) + acc + bias; LN across row (quad reduce)
        float s0 = 0.f, q0 = 0.f, s1 = 0.f, q1 = 0.f;
        #pragma unroll
        for (int nt = 0; nt < 16; nt++) {
            int col = nt * 8 + 2 * tig;
            float2 bb = *(const float2*)(bias + col);
            float2 h0 = v0 ? *(const float2*)(Store + (size_t)row0 * DD + col) : z2;
            float2 h1 = v1 ? *(const float2*)(Store + (size_t)row1 * DD + col) : z2;
            float v00 = h0.x + acc[nt][0] + bb.x;
            float v01 = h0.y + acc[nt][1] + bb.y;
            float v10 = h1.x + acc[nt][2] + bb.x;
            float v11 = h1.y + acc[nt][3] + bb.y;
            s0 += v00 + v01; q0 += v00 * v00 + v01 * v01;
            s1 += v10 + v11; q1 += v10 * v10 + v11 * v11;
        }
        #pragma unroll
        for (int o = 1; o <= 2; o <<= 1) {
            s0 += __shfl_xor_sync(0xFFFFFFFFu, s0, o);
            q0 += __shfl_xor_sync(0xFFFFFFFFu, q0, o);
            s1 += __shfl_xor_sync(0xFFFFFFFFu, s1, o);
            q1 += __shfl_xor_sync(0xFFFFFFFFu, q1, o);
        }
        float mu0 = s0 * (1.0f / 128.0f);
        float mu1 = s1 * (1.0f / 128.0f);
        float rs0 = rsqrtf(q0 * (1.0f / 128.0f) - mu0 * mu0 + 1e-5f);
        float rs1 = rsqrtf(q1 * (1.0f / 128.0f) - mu1 * mu1 + 1e-5f);
        #pragma unroll
        for (int nt = 0; nt < 16; nt++) {
            int col = nt * 8 + 2 * tig;
            float2 bb = *(const float2*)(bias + col);
            float2 gg = *(const float2*)(lng + col);
            float2 bt = *(const float2*)(lnb + col);
            if (v0) {
                float2 h0 = *(const float2*)(Store + (size_t)row0 * DD + col);
                float v00 = h0.x + acc[nt][0] + bb.x;
                float v01 = h0.y + acc[nt][1] + bb.y;
                *(float2*)(C + (size_t)row0 * DD + col) =
                    make_float2((v00 - mu0) * rs0 * gg.x + bt.x,
                                (v01 - mu0) * rs0 * gg.y + bt.y);
            }
            if (v1) {
                float2 h1 = *(const float2*)(Store + (size_t)row1 * DD + col);
                float v10 = h1.x + acc[nt][2] + bb.x;
                float v11 = h1.y + acc[nt][3] + bb.y;
                *(float2*)(C + (size_t)row1 * DD + col) =
                    make_float2((v10 - mu1) * rs1 * gg.x + bt.x,
                                (v11 - mu1) * rs1 * gg.y + bt.y);
            }
        }
    }
}

// ---------------- aggregation: warp per node, uint2 gathers ----------------------
__global__ __launch_bounds__(256) void agg_k(
    const float* __restrict__ h32, const uint2* __restrict__ h16,
    const float* __restrict__ bias, float* __restrict__ out)
{
    int n = blockIdx.x * 8 + (threadIdx.x >> 5);
    if (n >= NN) return;
    int l = threadIdx.x & 31;

    float di = g_dinv[n];
    float dii = di * di;
    float4 self = *(const float4*)(h32 + (size_t)n * DD + 4 * l);
    float4 bb   = *(const float4*)(bias + 4 * l);
    float a0 = fmaf(self.x, dii, bb.x);
    float a1 = fmaf(self.y, dii, bb.y);
    float a2 = fmaf(self.z, dii, bb.z);
    float a3 = fmaf(self.w, dii, bb.w);

    int j = g_off[n], e = g_off[n + 1];
    for (; j + 4 <= e; j += 4) {
        int   s0 = g_src[j],     s1 = g_src[j + 1];
        int   s2 = g_src[j + 2], s3 = g_src[j + 3];
        float w0 = g_wt[j],      w1 = g_wt[j + 1];
        float w2 = g_wt[j + 2],  w3 = g_wt[j + 3];
        uint2 u0 = h16[(size_t)s0 * 32 + l];
        uint2 u1 = h16[(size_t)s1 * 32 + l];
        uint2 u2 = h16[(size_t)s2 * 32 + l];
        uint2 u3 = h16[(size_t)s3 * 32 + l];
        float2 fa, fb;
        fa = __half22float2(*(const __half2*)&u0.x); fb = __half22float2(*(const __half2*)&u0.y);
        a0 = fmaf(fa.x, w0, a0); a1 = fmaf(fa.y, w0, a1);
        a2 = fmaf(fb.x, w0, a2); a3 = fmaf(fb.y, w0, a3);
        fa = __half22float2(*(const __half2*)&u1.x); fb = __half22float2(*(const __half2*)&u1.y);
        a0 = fmaf(fa.x, w1, a0); a1 = fmaf(fa.y, w1, a1);
        a2 = fmaf(fb.x, w1, a2); a3 = fmaf(fb.y, w1, a3);
        fa = __half22float2(*(const __half2*)&u2.x); fb = __half22float2(*(const __half2*)&u2.y);
        a0 = fmaf(fa.x, w2, a0); a1 = fmaf(fa.y, w2, a1);
        a2 = fmaf(fb.x, w2, a2); a3 = fmaf(fb.y, w2, a3);
        fa = __half22float2(*(const __half2*)&u3.x); fb = __half22float2(*(const __half2*)&u3.y);
        a0 = fmaf(fa.x, w3, a0); a1 = fmaf(fa.y, w3, a1);
        a2 = fmaf(fb.x, w3, a2); a3 = fmaf(fb.y, w3, a3);
    }
    for (; j < e; ++j) {
        float w = g_wt[j];
        uint2 u = h16[(size_t)g_src[j] * 32 + l];
        float2 fa = __half22float2(*(const __half2*)&u.x);
        float2 fb = __half22float2(*(const __half2*)&u.y);
        a0 = fmaf(fa.x, w, a0); a1 = fmaf(fa.y, w, a1);
        a2 = fmaf(fb.x, w, a2); a3 = fmaf(fb.y, w, a3);
    }
    *(float4*)(out + (size_t)n * DD + 4 * l) = make_float4(a0, a1, a2, a3);
}

// ---------------- BatchNorm stats (atomic-free partials) -------------------------
__global__ void bnstats_k(const float* __restrict__ x) {
    int t = threadIdx.x;
    float s = 0.0f, q = 0.0f;
    for (int r = blockIdx.x; r < NN; r += gridDim.x) {
        float v = x[(size_t)r * DD + t];
        s += v; q += v * v;
    }
    g_psum[blockIdx.x * DD + t] = s;
    g_psq[blockIdx.x * DD + t]  = q;
}

__global__ void bnprep_k(const float* __restrict__ g, const float* __restrict__ be) {
    int c = blockIdx.x;
    int t = threadIdx.x;
    float s = 0.0f, q = 0.0f;
    for (int p = t; p < 512; p += 128) {
        s += g_psum[p * DD + c];
        q += g_psq[p * DD + c];
    }
    #pragma unroll
    for (int o = 16; o > 0; o >>= 1) {
        s += __shfl_xor_sync(0xFFFFFFFFu, s, o);
        q += __shfl_xor_sync(0xFFFFFFFFu, q, o);
    }
    __shared__ float ss[4], qq[4];
    if ((t & 31) == 0) { ss[t >> 5] = s; qq[t >> 5] = q; }
    __syncthreads();
    if (t == 0) {
        s = ss[0] + ss[1] + ss[2] + ss[3];
        q = qq[0] + qq[1] + qq[2] + qq[3];
        float mu  = s * (1.0f / NN);
        float var = q * (1.0f / NN) - mu * mu;
        float sc  = g[c] * rsqrtf(var + 1e-5f);
        g_scale[c] = sc;
        g_shift[c] = be[c] - mu * sc;
    }
}

// ---------------- launch ----------------
extern "C" void kernel_launch(void* const* d_in, const int* in_sizes, int n_in,
                              void* d_out, int out_size) {
    const float* x  = (const float*)d_in[0];
    const int*   ei = (const int*)d_in[1];   // int32 (JAX x64-disabled)
    const float* W0 = (const float*)d_in[2];  const float* b0 = (const float*)d_in[3];
    const float* W1 = (const float*)d_in[4];  const float* b1 = (const float*)d_in[5];
    const float* W2 = (const float*)d_in[6];  const float* b2 = (const float*)d_in[7];
    const float* g0 = (const float*)d_in[8];  const float* be0 = (const float*)d_in[9];
    const float* g1 = (const float*)d_in[10]; const float* be1 = (const float*)d_in[11];
    const float* Wv = (const float*)d_in[12]; const float* bv = (const float*)d_in[13];
    const float* Wo = (const float*)d_in[14]; const float* bo = (const float*)d_in[15];
    const float* lng = (const float*)d_in[16]; const float* lnb = (const float*)d_in[17];
    float* out = (float*)d_out;

    void *pA, *pB, *pC, *pH, *pWh, *pWl, *pBvo;
    cudaGetSymbolAddress(&pA, g_bufA);
    cudaGetSymbolAddress(&pB, g_bufB);
    cudaGetSymbolAddress(&pC, g_bufC);
    cudaGetSymbolAddress(&pH, g_h16);
    cudaGetSymbolAddress(&pWh, g_wth);
    cudaGetSymbolAddress(&pWl, g_wtl);
    cudaGetSymbolAddress(&pBvo, g_bvo);
    float* A = (float*)pA;
    float* B = (float*)pB;
    float* C = (float*)pC;
    __half2* H16 = (__half2*)pH;
    const uint2* H16u = (const uint2*)pH;
    const unsigned short* Wh = (const unsigned short*)pWh;
    const unsigned short* Wl = (const unsigned short*)pWl;
    const float* bvo = (const float*)pBvo;

    const int* rowp = ei;
    const int* colp = ei + EE;

    const int SCAN_BLOCKS = (NN + 1023) / 1024;   // 98
    const int GEMM_BLOCKS = (NN + 127) / 128;     // 782
    const int AGG_BLOCKS  = (NN + 7) / 8;         // 12500
    const int SMEM_W = 2 * DD * WT_STRIDE * 4 + 2 * DD * 4;   // 70656 B

    static int smem_set = 0;
    if (!smem_set) {
        cudaFuncSetAttribute(gemm_tc, cudaFuncAttributeMaxDynamicSharedMemorySize, SMEM_W);
        smem_set = 1;
    }

    // --- graph prep + weight prep ---
    zero_counts_k<<<(NN + 255) / 256, 256>>>();
    hist_k<<<2048, 256>>>(colp);
    scan1_k<<<SCAN_BLOCKS, 1024>>>();
    scan2_k<<<1, 128>>>(SCAN_BLOCKS);
    scan3_k<<<SCAN_BLOCKS, 1024>>>();
    scatter_k<<<2048, 256>>>(rowp, colp);
    wsplit_k<<<(3 * DD * DD + 255) / 256, 256>>>(W0, W1, W2);
    wvo_k<<<129, 128>>>(Wv, bv, Wo, bo);

    const unsigned short* Wh0 = Wh;               const unsigned short* Wl0 = Wl;
    const unsigned short* Wh1 = Wh + 1 * DD * DD; const unsigned short* Wl1 = Wl + 1 * DD * DD;
    const unsigned short* Wh2 = Wh + 2 * DD * DD; const unsigned short* Wl2 = Wl + 2 * DD * DD;
    const unsigned short* Whv = Wh + 3 * DD * DD; const unsigned short* Wlv = Wl + 3 * DD * DD;

    // --- layer 0: A1 = x@W0 ; B1 = agg(A1) ; BN stats ---
    gemm_tc<<<GEMM_BLOCKS, 256, SMEM_W>>>(x, nullptr, nullptr, Wh0, Wl0,
                                          nullptr, nullptr, nullptr, A, H16, NN);
    agg_k<<<AGG_BLOCKS, 256>>>(A, H16u, b0, B);
    bnstats_k<<<512, 128>>>(B);
    bnprep_k<<<DD, 128>>>(g0, be0);

    // --- layer 1: fused BN0 apply in prologue (C = layer0 out), A2 = C@W1 ---
    gemm_tc<<<GEMM_BLOCKS, 256, SMEM_W>>>(B, x, C, Wh1, Wl1,
                                          nullptr, nullptr, nullptr, A, H16, NN);
    agg_k<<<AGG_BLOCKS, 256>>>(A, H16u, b1, B);
    bnstats_k<<<512, 128>>>(B);
    bnprep_k<<<DD, 128>>>(g1, be1);

    // --- attention + LN: H = relu(bn(B2))+C (stored to A); att = H@Wvo + bvo ;
    //     C = LN(H + att) ---
    gemm_tc<<<GEMM_BLOCKS, 256, SMEM_W>>>(B, C, A, Whv, Wlv,
                                          bvo, lng, lnb, C, nullptr, NN);

    // --- output conv: A3 = C@W2 ; out = agg(A3) ---
    gemm_tc<<<GEMM_BLOCKS, 256, SMEM_W>>>(C, nullptr, nullptr, Wh2, Wl2,
                                          nullptr, nullptr, nullptr, A, H16, NN);
    agg_k<<<AGG_BLOCKS, 256>>>(A, H16u, b2, out);
}

// round 11
// speedup vs baseline: 2.6440x; 1.2013x over previous
#include <cuda_runtime.h>
#include <cuda_fp16.h>
#include <cuda_bf16.h>
#include <cstdint>

#define NN 100000
#define EE 1600000
#define DD 128
#define AGG_BLOCKS 12500   // NN / 8 exactly

// ---------------- scratch (device globals; no runtime allocation) ----------------
__device__ float g_bufA[(size_t)NN * DD];
__device__ float g_bufB[(size_t)NN * DD];
__device__ float g_bufC[(size_t)NN * DD];
__device__ uint2 g_h16[(size_t)NN * 32];        // fp16 shadow table (row = 32 uint2)
__device__ unsigned short g_wth[4 * DD * DD];   // W^T hi (bf16 bits): W0,W1,W2,Wvo
__device__ unsigned short g_wtl[4 * DD * DD];   // W^T lo
__device__ float g_bvo[DD];
__device__ int   g_counts[NN];
__device__ int   g_off[NN + 1];
__device__ int   g_cursor[NN];
__device__ int   g_bsums[128];
__device__ float g_dinv[NN];
__device__ uint2 g_edge[EE];                    // (src, weight bits)
__device__ float g_psum[AGG_BLOCKS * DD];
__device__ float g_psq[AGG_BLOCKS * DD];
__device__ float g_psum2[128 * DD];
__device__ float g_psq2[128 * DD];
__device__ float g_scale[DD];
__device__ float g_shift[DD];

// ---------------- graph preprocessing ----------------

__global__ void zero_counts_k() {
    int i = blockIdx.x * blockDim.x + threadIdx.x;
    if (i < NN) g_counts[i] = 0;
}

__global__ void hist_k(const int* __restrict__ colp) {
    int i = blockIdx.x * blockDim.x + threadIdx.x;
    int stride = gridDim.x * blockDim.x;
    for (; i < EE; i += stride) atomicAdd(&g_counts[colp[i]], 1);
}

// block scan (+ dinv fused)
__global__ void scan1_k() {
    __shared__ int sh[1024];
    int i = blockIdx.x * 1024 + threadIdx.x;
    int v = (i < NN) ? g_counts[i] : 0;
    if (i < NN) g_dinv[i] = rsqrtf((float)v + 1.0f);
    sh[threadIdx.x] = v;
    __syncthreads();
    #pragma unroll
    for (int o = 1; o < 1024; o <<= 1) {
        int t = (threadIdx.x >= o) ? sh[threadIdx.x - o] : 0;
        __syncthreads();
        sh[threadIdx.x] += t;
        __syncthreads();
    }
    if (i < NN) g_off[i] = sh[threadIdx.x] - v;
    if (threadIdx.x == 1023) g_bsums[blockIdx.x] = sh[1023];
}

__global__ void scan2_k(int nb) {
    __shared__ int sh[128];
    int t = threadIdx.x;
    int v = (t < nb) ? g_bsums[t] : 0;
    sh[t] = v;
    __syncthreads();
    #pragma unroll
    for (int o = 1; o < 128; o <<= 1) {
        int tv = (t >= o) ? sh[t - o] : 0;
        __syncthreads();
        sh[t] += tv;
        __syncthreads();
    }
    if (t < nb) g_bsums[t] = sh[t] - v;
}

__global__ void scan3_k() {
    int i = blockIdx.x * 1024 + threadIdx.x;
    if (i < NN) {
        int v = g_off[i] + g_bsums[blockIdx.x];
        g_off[i] = v;
        g_cursor[i] = v;
    }
    if (i == 0) g_off[NN] = EE;
}

__global__ void scatter_k(const int* __restrict__ rowp,
                          const int* __restrict__ colp) {
    int i = blockIdx.x * blockDim.x + threadIdx.x;
    int stride = gridDim.x * blockDim.x;
    for (; i < EE; i += stride) {
        int r = rowp[i];
        int c = colp[i];
        float w = g_dinv[r] * g_dinv[c];
        int p = atomicAdd(&g_cursor[c], 1);
        g_edge[p] = make_uint2((unsigned)r, __float_as_uint(w));
    }
}

// ---------------- W split: slots 0,1,2 = W0,W1,W2 transposed hi/lo ---------------
__global__ void wsplit_k(const float* __restrict__ W0, const float* __restrict__ W1,
                         const float* __restrict__ W2) {
    int gidx = blockIdx.x * blockDim.x + threadIdx.x;
    if (gidx >= 3 * DD * DD) return;
    int m = gidx / (DD * DD);
    int idx = gidx - m * (DD * DD);
    const float* W = (m == 0) ? W0 : (m == 1) ? W1 : W2;
    int k = idx >> 7, n = idx & 127;
    float w = W[idx];
    __nv_bfloat16 h = __float2bfloat16_rn(w);
    float hf = __bfloat162float(h);
    __nv_bfloat16 l = __float2bfloat16_rn(w - hf);
    g_wth[m * DD * DD + n * DD + k] = __bfloat16_as_ushort(h);
    g_wtl[m * DD * DD + n * DD + k] = __bfloat16_as_ushort(l);
}

// ---------------- Wvo = Wv @ Wo (slot 3), bvo = bv @ Wo + bo ---------------------
__global__ void wvo_k(const float* __restrict__ Wv, const float* __restrict__ bv,
                      const float* __restrict__ Wo, const float* __restrict__ bo) {
    __shared__ float rowv[128];
    int t = threadIdx.x;
    if (blockIdx.x < 128) {
        int i = blockIdx.x;
        rowv[t] = Wv[i * 128 + t];
        __syncthreads();
        float s = 0.0f;
        #pragma unroll 8
        for (int k = 0; k < 128; k++) s += rowv[k] * Wo[k * 128 + t];
        __nv_bfloat16 h = __float2bfloat16_rn(s);
        float hf = __bfloat162float(h);
        __nv_bfloat16 l = __float2bfloat16_rn(s - hf);
        g_wth[3 * DD * DD + t * DD + i] = __bfloat16_as_ushort(h);
        g_wtl[3 * DD * DD + t * DD + i] = __bfloat16_as_ushort(l);
    } else {
        float s = bo[t];
        #pragma unroll 8
        for (int k = 0; k < 128; k++) s += bv[k] * Wo[k * 128 + t];
        g_bvo[t] = s;
    }
}

// ---------------- tensor-core GEMM (fused prologue/epilogue variants) ------------
//  - Res != null : a = relu(Ain*scale+shift) + Res (BN apply), stored to Store.
//  - lng != null : LayerNorm epilogue: C = LN(Store + acc + bias) per row.
//  - C == null   : skip fp32 output write (h16-only conv GEMM).
//  - C16 != null : write half2 shadow copy.

__device__ __forceinline__ unsigned pack_bf16x2(float lo_elem, float hi_elem) {
    unsigned r;
    asm("cvt.rn.bf16x2.f32 %0, %1, %2;" : "=r"(r) : "f"(hi_elem), "f"(lo_elem));
    return r;
}

__device__ __forceinline__ void mma16816(float* c, const unsigned* a,
                                         unsigned b0, unsigned b1) {
    asm volatile(
        "mma.sync.aligned.m16n8k16.row.col.f32.bf16.bf16.f32 "
        "{%0,%1,%2,%3}, {%4,%5,%6,%7}, {%8,%9}, {%0,%1,%2,%3};"
        : "+f"(c[0]), "+f"(c[1]), "+f"(c[2]), "+f"(c[3])
        : "r"(a[0]), "r"(a[1]), "r"(a[2]), "r"(a[3]), "r"(b0), "r"(b1));
}

__device__ __forceinline__ void split2(float2 x, unsigned& hi, unsigned& lo) {
    hi = pack_bf16x2(x.x, x.y);
    float h0 = __uint_as_float(hi << 16);
    float h1 = __uint_as_float(hi & 0xFFFF0000u);
    lo = pack_bf16x2(x.x - h0, x.y - h1);
}

#define WT_STRIDE 68

__global__ __launch_bounds__(256) void gemm_tc(
    const float* __restrict__ Ain, const float* __restrict__ Res,
    float* __restrict__ Store,
    const unsigned short* __restrict__ Wthi, const unsigned short* __restrict__ Wtlo,
    const float* __restrict__ bias,
    const float* __restrict__ lng, const float* __restrict__ lnb,
    float* __restrict__ C, __half2* __restrict__ C16, int M)
{
    extern __shared__ unsigned smw[];
    unsigned* WhiS = smw;
    unsigned* WloS = smw + DD * WT_STRIDE;
    float* sSc = (float*)(smw + 2 * DD * WT_STRIDE);
    float* sSh = sSc + DD;

    int tid = threadIdx.x;
    const unsigned* ghi = (const unsigned*)Wthi;
    const unsigned* glo = (const unsigned*)Wtlo;
    #pragma unroll
    for (int i = tid; i < DD * 64; i += 256) {
        int n = i >> 6, kw = i & 63;
        WhiS[n * WT_STRIDE + kw] = ghi[i];
        WloS[n * WT_STRIDE + kw] = glo[i];
    }
    if (Res && tid < 128) { sSc[tid] = g_scale[tid]; sSh[tid] = g_shift[tid]; }
    __syncthreads();

    int warp = tid >> 5, lane = tid & 31;
    int g = lane >> 2, tig = lane & 3;
    int row0 = blockIdx.x * 128 + warp * 16 + g;
    int row1 = row0 + 8;
    bool v0 = row0 < M, v1 = row1 < M;
    const float* ar0 = Ain + (size_t)row0 * DD;
    const float* ar1 = Ain + (size_t)row1 * DD;

    float acc[16][4];
    #pragma unroll
    for (int nt = 0; nt < 16; nt++)
        #pragma unroll
        for (int i = 0; i < 4; i++) acc[nt][i] = 0.0f;

    const float2 z2 = make_float2(0.f, 0.f);

    #pragma unroll
    for (int kc = 0; kc < 8; kc++) {
        int k0 = kc * 16 + 2 * tig;
        float2 x0 = v0 ? *(const float2*)(ar0 + k0)     : z2;
        float2 x1 = v1 ? *(const float2*)(ar1 + k0)     : z2;
        float2 x2 = v0 ? *(const float2*)(ar0 + k0 + 8) : z2;
        float2 x3 = v1 ? *(const float2*)(ar1 + k0 + 8) : z2;

        if (Res) {
            float2 scA = make_float2(sSc[k0], sSc[k0 + 1]);
            float2 shA = make_float2(sSh[k0], sSh[k0 + 1]);
            float2 scB = make_float2(sSc[k0 + 8], sSc[k0 + 9]);
            float2 shB = make_float2(sSh[k0 + 8], sSh[k0 + 9]);
            float2 r0 = v0 ? *(const float2*)(Res + (size_t)row0 * DD + k0)     : z2;
            float2 r1 = v1 ? *(const float2*)(Res + (size_t)row1 * DD + k0)     : z2;
            float2 r2 = v0 ? *(const float2*)(Res + (size_t)row0 * DD + k0 + 8) : z2;
            float2 r3 = v1 ? *(const float2*)(Res + (size_t)row1 * DD + k0 + 8) : z2;
            x0.x = fmaxf(fmaf(x0.x, scA.x, shA.x), 0.f) + r0.x;
            x0.y = fmaxf(fmaf(x0.y, scA.y, shA.y), 0.f) + r0.y;
            x1.x = fmaxf(fmaf(x1.x, scA.x, shA.x), 0.f) + r1.x;
            x1.y = fmaxf(fmaf(x1.y, scA.y, shA.y), 0.f) + r1.y;
            x2.x = fmaxf(fmaf(x2.x, scB.x, shB.x), 0.f) + r2.x;
            x2.y = fmaxf(fmaf(x2.y, scB.y, shB.y), 0.f) + r2.y;
            x3.x = fmaxf(fmaf(x3.x, scB.x, shB.x), 0.f) + r3.x;
            x3.y = fmaxf(fmaf(x3.y, scB.y, shB.y), 0.f) + r3.y;
            if (v0) {
                *(float2*)(Store + (size_t)row0 * DD + k0)     = x0;
                *(float2*)(Store + (size_t)row0 * DD + k0 + 8) = x2;
            }
            if (v1) {
                *(float2*)(Store + (size_t)row1 * DD + k0)     = x1;
                *(float2*)(Store + (size_t)row1 * DD + k0 + 8) = x3;
            }
        }

        unsigned ahi[4], alo[4];
        split2(x0, ahi[0], alo[0]);
        split2(x1, ahi[1], alo[1]);
        split2(x2, ahi[2], alo[2]);
        split2(x3, ahi[3], alo[3]);

        int kw = kc * 8 + tig;
        #pragma unroll
        for (int nt = 0; nt < 16; nt++) {
            int nrow = (nt * 8 + g) * WT_STRIDE + kw;
            unsigned bh0 = WhiS[nrow];
            unsigned bh1 = WhiS[nrow + 4];
            unsigned bl0 = WloS[nrow];
            unsigned bl1 = WloS[nrow + 4];
            mma16816(acc[nt], ahi, bh0, bh1);
            mma16816(acc[nt], ahi, bl0, bl1);
            mma16816(acc[nt], alo, bh0, bh1);
        }
    }

    if (!lng) {
        #pragma unroll
        for (int nt = 0; nt < 16; nt++) {
            int col = nt * 8 + 2 * tig;
            float2 bb = bias ? *(const float2*)(bias + col) : z2;
            float o0 = acc[nt][0] + bb.x, o1 = acc[nt][1] + bb.y;
            float o2 = acc[nt][2] + bb.x, o3 = acc[nt][3] + bb.y;
            if (v0) {
                if (C)   *(float2*)(C + (size_t)row0 * DD + col) = make_float2(o0, o1);
                if (C16) C16[(size_t)row0 * 64 + (col >> 1)] = __floats2half2_rn(o0, o1);
            }
            if (v1) {
                if (C)   *(float2*)(C + (size_t)row1 * DD + col) = make_float2(o2, o3);
                if (C16) C16[(size_t)row1 * 64 + (col >> 1)] = __floats2half2_rn(o2, o3);
            }
        }
    } else {
        // LayerNorm epilogue: v = Store(row) + acc + bias; LN across row (quad reduce)
        float s0 = 0.f, q0 = 0.f, s1 = 0.f, q1 = 0.f;
        #pragma unroll
        for (int nt = 0; nt < 16; nt++) {
            int col = nt * 8 + 2 * tig;
            float2 bb = *(const float2*)(bias + col);
            float2 h0 = v0 ? *(const float2*)(Store + (size_t)row0 * DD + col) : z2;
            float2 h1 = v1 ? *(const float2*)(Store + (size_t)row1 * DD + col) : z2;
            float v00 = h0.x + acc[nt][0] + bb.x;
            float v01 = h0.y + acc[nt][1] + bb.y;
            float v10 = h1.x + acc[nt][2] + bb.x;
            float v11 = h1.y + acc[nt][3] + bb.y;
            s0 += v00 + v01; q0 += v00 * v00 + v01 * v01;
            s1 += v10 + v11; q1 += v10 * v10 + v11 * v11;
        }
        #pragma unroll
        for (int o = 1; o <= 2; o <<= 1) {
            s0 += __shfl_xor_sync(0xFFFFFFFFu, s0, o);
            q0 += __shfl_xor_sync(0xFFFFFFFFu, q0, o);
            s1 += __shfl_xor_sync(0xFFFFFFFFu, s1, o);
            q1 += __shfl_xor_sync(0xFFFFFFFFu, q1, o);
        }
        float mu0 = s0 * (1.0f / 128.0f);
        float mu1 = s1 * (1.0f / 128.0f);
        float rs0 = rsqrtf(q0 * (1.0f / 128.0f) - mu0 * mu0 + 1e-5f);
        float rs1 = rsqrtf(q1 * (1.0f / 128.0f) - mu1 * mu1 + 1e-5f);
        #pragma unroll
        for (int nt = 0; nt < 16; nt++) {
            int col = nt * 8 + 2 * tig;
            float2 bb = *(const float2*)(bias + col);
            float2 gg = *(const float2*)(lng + col);
            float2 bt = *(const float2*)(lnb + col);
            if (v0) {
                float2 h0 = *(const float2*)(Store + (size_t)row0 * DD + col);
                float v00 = h0.x + acc[nt][0] + bb.x;
                float v01 = h0.y + acc[nt][1] + bb.y;
                *(float2*)(C + (size_t)row0 * DD + col) =
                    make_float2((v00 - mu0) * rs0 * gg.x + bt.x,
                                (v01 - mu0) * rs0 * gg.y + bt.y);
            }
            if (v1) {
                float2 h1 = *(const float2*)(Store + (size_t)row1 * DD + col);
                float v10 = h1.x + acc[nt][2] + bb.x;
                float v11 = h1.y + acc[nt][3] + bb.y;
                *(float2*)(C + (size_t)row1 * DD + col) =
                    make_float2((v10 - mu1) * rs1 * gg.x + bt.x,
                                (v11 - mu1) * rs1 * gg.y + bt.y);
            }
        }
    }
}

// ---------------- aggregation: warp per node, fp16 self + gathers ----------------
// Optional fused BN partial stats (per-block column sums into g_psum/g_psq).
__global__ __launch_bounds__(256) void agg_k(
    const uint2* __restrict__ h16, const float* __restrict__ bias,
    float* __restrict__ out, int doStats)
{
    __shared__ float sPart[8][DD];
    int w = threadIdx.x >> 5;
    int n = blockIdx.x * 8 + w;          // grid exactly covers NN
    int l = threadIdx.x & 31;

    float di = g_dinv[n];
    float dii = di * di;
    uint2 us = h16[(size_t)n * 32 + l];
    float2 sa = __half22float2(*(const __half2*)&us.x);
    float2 sb = __half22float2(*(const __half2*)&us.y);
    float4 bb = *(const float4*)(bias + 4 * l);
    float a0 = fmaf(sa.x, dii, bb.x);
    float a1 = fmaf(sa.y, dii, bb.y);
    float a2 = fmaf(sb.x, dii, bb.z);
    float a3 = fmaf(sb.y, dii, bb.w);

    int j = g_off[n], e = g_off[n + 1];
    for (; j + 4 <= e; j += 4) {
        uint2 e0 = g_edge[j],     e1 = g_edge[j + 1];
        uint2 e2 = g_edge[j + 2], e3 = g_edge[j + 3];
        float w0 = __uint_as_float(e0.y), w1 = __uint_as_float(e1.y);
        float w2 = __uint_as_float(e2.y), w3 = __uint_as_float(e3.y);
        uint2 u0 = h16[(size_t)e0.x * 32 + l];
        uint2 u1 = h16[(size_t)e1.x * 32 + l];
        uint2 u2 = h16[(size_t)e2.x * 32 + l];
        uint2 u3 = h16[(size_t)e3.x * 32 + l];
        float2 fa, fb;
        fa = __half22float2(*(const __half2*)&u0.x); fb = __half22float2(*(const __half2*)&u0.y);
        a0 = fmaf(fa.x, w0, a0); a1 = fmaf(fa.y, w0, a1);
        a2 = fmaf(fb.x, w0, a2); a3 = fmaf(fb.y, w0, a3);
        fa = __half22float2(*(const __half2*)&u1.x); fb = __half22float2(*(const __half2*)&u1.y);
        a0 = fmaf(fa.x, w1, a0); a1 = fmaf(fa.y, w1, a1);
        a2 = fmaf(fb.x, w1, a2); a3 = fmaf(fb.y, w1, a3);
        fa = __half22float2(*(const __half2*)&u2.x); fb = __half22float2(*(const __half2*)&u2.y);
        a0 = fmaf(fa.x, w2, a0); a1 = fmaf(fa.y, w2, a1);
        a2 = fmaf(fb.x, w2, a2); a3 = fmaf(fb.y, w2, a3);
        fa = __half22float2(*(const __half2*)&u3.x); fb = __half22float2(*(const __half2*)&u3.y);
        a0 = fmaf(fa.x, w3, a0); a1 = fmaf(fa.y, w3, a1);
        a2 = fmaf(fb.x, w3, a2); a3 = fmaf(fb.y, w3, a3);
    }
    for (; j < e; ++j) {
        uint2 ed = g_edge[j];
        float w = __uint_as_float(ed.y);
        uint2 u = h16[(size_t)ed.x * 32 + l];
        float2 fa = __half22float2(*(const __half2*)&u.x);
        float2 fb = __half22float2(*(const __half2*)&u.y);
        a0 = fmaf(fa.x, w, a0); a1 = fmaf(fa.y, w, a1);
        a2 = fmaf(fb.x, w, a2); a3 = fmaf(fb.y, w, a3);
    }
    *(float4*)(out + (size_t)n * DD + 4 * l) = make_float4(a0, a1, a2, a3);

    if (doStats) {
        *(float4*)&sPart[w][4 * l] = make_float4(a0, a1, a2, a3);
        __syncthreads();
        int t = threadIdx.x;
        if (t < DD) {
            float s = 0.f, q = 0.f;
            #pragma unroll
            for (int ww = 0; ww < 8; ww++) {
                float v = sPart[ww][t];
                s += v; q += v * v;
            }
            g_psum[blockIdx.x * DD + t] = s;
            g_psq[blockIdx.x * DD + t]  = q;
        }
    }
}

// ---------------- BN stat reduction: 12500 partial rows -> 128 -> scale/shift ----
__global__ void reduce1_k() {
    int b = blockIdx.x;       // 0..127
    int t = threadIdx.x;      // 0..127
    int start = b * 98;
    int end = start + 98; if (end > AGG_BLOCKS) end = AGG_BLOCKS;
    float s = 0.f, q = 0.f;
    for (int p = start; p < end; p++) {
        s += g_psum[p * DD + t];
        q += g_psq[p * DD + t];
    }
    g_psum2[b * DD + t] = s;
    g_psq2[b * DD + t]  = q;
}

__global__ void bnprep_k(const float* __restrict__ g, const float* __restrict__ be) {
    int t = threadIdx.x;      // 128 threads, one per column
    float s = 0.f, q = 0.f;
    for (int p = 0; p < 128; p++) {
        s += g_psum2[p * DD + t];
        q += g_psq2[p * DD + t];
    }
    float mu  = s * (1.0f / NN);
    float var = q * (1.0f / NN) - mu * mu;
    float sc  = g[t] * rsqrtf(var + 1e-5f);
    g_scale[t] = sc;
    g_shift[t] = be[t] - mu * sc;
}

// ---------------- launch ----------------
extern "C" void kernel_launch(void* const* d_in, const int* in_sizes, int n_in,
                              void* d_out, int out_size) {
    const float* x  = (const float*)d_in[0];
    const int*   ei = (const int*)d_in[1];   // int32 (JAX x64-disabled)
    const float* W0 = (const float*)d_in[2];  const float* b0 = (const float*)d_in[3];
    const float* W1 = (const float*)d_in[4];  const float* b1 = (const float*)d_in[5];
    const float* W2 = (const float*)d_in[6];  const float* b2 = (const float*)d_in[7];
    const float* g0 = (const float*)d_in[8];  const float* be0 = (const float*)d_in[9];
    const float* g1 = (const float*)d_in[10]; const float* be1 = (const float*)d_in[11];
    const float* Wv = (const float*)d_in[12]; const float* bv = (const float*)d_in[13];
    const float* Wo = (const float*)d_in[14]; const float* bo = (const float*)d_in[15];
    const float* lng = (const float*)d_in[16]; const float* lnb = (const float*)d_in[17];
    float* out = (float*)d_out;

    void *pA, *pB, *pC, *pH, *pWh, *pWl, *pBvo;
    cudaGetSymbolAddress(&pA, g_bufA);
    cudaGetSymbolAddress(&pB, g_bufB);
    cudaGetSymbolAddress(&pC, g_bufC);
    cudaGetSymbolAddress(&pH, g_h16);
    cudaGetSymbolAddress(&pWh, g_wth);
    cudaGetSymbolAddress(&pWl, g_wtl);
    cudaGetSymbolAddress(&pBvo, g_bvo);
    float* A = (float*)pA;
    float* B = (float*)pB;
    float* C = (float*)pC;
    __half2* H16 = (__half2*)pH;
    const uint2* H16u = (const uint2*)pH;
    const unsigned short* Wh = (const unsigned short*)pWh;
    const unsigned short* Wl = (const unsigned short*)pWl;
    const float* bvo = (const float*)pBvo;

    const int* rowp = ei;
    const int* colp = ei + EE;

    const int SCAN_BLOCKS = (NN + 1023) / 1024;   // 98
    const int GEMM_BLOCKS = (NN + 127) / 128;     // 782
    const int SMEM_W = 2 * DD * WT_STRIDE * 4 + 2 * DD * 4;   // 70656 B

    static int smem_set = 0;
    if (!smem_set) {
        cudaFuncSetAttribute(gemm_tc, cudaFuncAttributeMaxDynamicSharedMemorySize, SMEM_W);
        smem_set = 1;
    }

    // --- graph prep + weight prep ---
    zero_counts_k<<<(NN + 255) / 256, 256>>>();
    hist_k<<<2048, 256>>>(colp);
    scan1_k<<<SCAN_BLOCKS, 1024>>>();
    scan2_k<<<1, 128>>>(SCAN_BLOCKS);
    scan3_k<<<SCAN_BLOCKS, 1024>>>();
    scatter_k<<<2048, 256>>>(rowp, colp);
    wsplit_k<<<(3 * DD * DD + 255) / 256, 256>>>(W0, W1, W2);
    wvo_k<<<129, 128>>>(Wv, bv, Wo, bo);

    const unsigned short* Wh0 = Wh;               const unsigned short* Wl0 = Wl;
    const unsigned short* Wh1 = Wh + 1 * DD * DD; const unsigned short* Wl1 = Wl + 1 * DD * DD;
    const unsigned short* Wh2 = Wh + 2 * DD * DD; const unsigned short* Wl2 = Wl + 2 * DD * DD;
    const unsigned short* Whv = Wh + 3 * DD * DD; const unsigned short* Wlv = Wl + 3 * DD * DD;

    // --- layer 0: h16 = fp16(x@W0); B = agg(h16) with fused BN stats ---
    gemm_tc<<<GEMM_BLOCKS, 256, SMEM_W>>>(x, nullptr, nullptr, Wh0, Wl0,
                                          nullptr, nullptr, nullptr, nullptr, H16, NN);
    agg_k<<<AGG_BLOCKS, 256>>>(H16u, b0, B, 1);
    reduce1_k<<<128, 128>>>();
    bnprep_k<<<1, 128>>>(g0, be0);

    // --- layer 1: fused BN0 apply in prologue (C = layer0 out), h16 = fp16(C@W1) --
    gemm_tc<<<GEMM_BLOCKS, 256, SMEM_W>>>(B, x, C, Wh1, Wl1,
                                          nullptr, nullptr, nullptr, nullptr, H16, NN);
    agg_k<<<AGG_BLOCKS, 256>>>(H16u, b1, B, 1);
    reduce1_k<<<128, 128>>>();
    bnprep_k<<<1, 128>>>(g1, be1);

    // --- attention + LN: H = relu(bn(B))+C (stored to A); att = H@Wvo + bvo ;
    //     C = LN(H + att) ---
    gemm_tc<<<GEMM_BLOCKS, 256, SMEM_W>>>(B, C, A, Whv, Wlv,
                                          bvo, lng, lnb, C, nullptr, NN);

    // --- output conv: h16 = fp16(C@W2) ; out = agg(h16) ---
    gemm_tc<<<GEMM_BLOCKS, 256, SMEM_W>>>(C, nullptr, nullptr, Wh2, Wl2,
                                          nullptr, nullptr, nullptr, nullptr, H16, NN);
    agg_k<<<AGG_BLOCKS, 256>>>(H16u, b2, out, 0);
}

// round 12
// speedup vs baseline: 3.0408x; 1.1501x over previous
#include <cuda_runtime.h>
#include <cuda_fp16.h>
#include <cuda_bf16.h>
#include <cstdint>

#define NN 100000
#define EE 1600000
#define DD 128
#define AGG_BLOCKS 12500   // NN / 8 exactly

// ---------------- scratch (device globals; no runtime allocation) ----------------
__device__ float g_bufA[(size_t)NN * DD];
__device__ float g_bufC[(size_t)NN * DD];
__device__ uint2 g_h16[(size_t)NN * 32];        // fp16 shadow table (GEMM out)
__device__ uint2 g_b16[(size_t)NN * 32];        // fp16 conv-agg output
__device__ unsigned short g_wth[4 * DD * DD];   // W^T hi (bf16 bits): W0,W1,W2,Wvo
__device__ unsigned short g_wtl[4 * DD * DD];   // W^T lo
__device__ float g_bvo[DD];
__device__ int   g_counts[NN];
__device__ int   g_off[NN + 1];
__device__ int   g_cursor[NN];
__device__ int   g_bsums[128];
__device__ float g_dinv[NN];
__device__ uint2 g_edge[EE];                    // (src, weight bits)
__device__ float g_psum[AGG_BLOCKS * DD];
__device__ float g_psq[AGG_BLOCKS * DD];
__device__ float g_psum2[128 * DD];
__device__ float g_psq2[128 * DD];
__device__ float g_scale[DD];
__device__ float g_shift[DD];
__device__ int   g_tick;

// ---------------- graph preprocessing ----------------

__global__ void zero_counts_k() {
    int i = blockIdx.x * blockDim.x + threadIdx.x;
    if (i < NN) g_counts[i] = 0;
}

__global__ void hist_k(const int* __restrict__ colp) {
    int i = blockIdx.x * blockDim.x + threadIdx.x;
    int stride = gridDim.x * blockDim.x;
    for (; i < EE; i += stride) atomicAdd(&g_counts[colp[i]], 1);
}

// block scan (+ dinv fused)
__global__ void scan1_k() {
    __shared__ int sh[1024];
    int i = blockIdx.x * 1024 + threadIdx.x;
    int v = (i < NN) ? g_counts[i] : 0;
    if (i < NN) g_dinv[i] = rsqrtf((float)v + 1.0f);
    sh[threadIdx.x] = v;
    __syncthreads();
    #pragma unroll
    for (int o = 1; o < 1024; o <<= 1) {
        int t = (threadIdx.x >= o) ? sh[threadIdx.x - o] : 0;
        __syncthreads();
        sh[threadIdx.x] += t;
        __syncthreads();
    }
    if (i < NN) g_off[i] = sh[threadIdx.x] - v;
    if (threadIdx.x == 1023) g_bsums[blockIdx.x] = sh[1023];
}

__global__ void scan2_k(int nb) {
    __shared__ int sh[128];
    int t = threadIdx.x;
    int v = (t < nb) ? g_bsums[t] : 0;
    sh[t] = v;
    __syncthreads();
    #pragma unroll
    for (int o = 1; o < 128; o <<= 1) {
        int tv = (t >= o) ? sh[t - o] : 0;
        __syncthreads();
        sh[t] += tv;
        __syncthreads();
    }
    if (t < nb) g_bsums[t] = sh[t] - v;
}

__global__ void scan3_k() {
    int i = blockIdx.x * 1024 + threadIdx.x;
    if (i < NN) {
        int v = g_off[i] + g_bsums[blockIdx.x];
        g_off[i] = v;
        g_cursor[i] = v;
    }
    if (i == 0) g_off[NN] = EE;
}

__global__ void scatter_k(const int* __restrict__ rowp,
                          const int* __restrict__ colp) {
    int i = blockIdx.x * blockDim.x + threadIdx.x;
    int stride = gridDim.x * blockDim.x;
    for (; i < EE; i += stride) {
        int r = rowp[i];
        int c = colp[i];
        float w = g_dinv[r] * g_dinv[c];
        int p = atomicAdd(&g_cursor[c], 1);
        g_edge[p] = make_uint2((unsigned)r, __float_as_uint(w));
    }
}

// ---------------- W split: slots 0,1,2 = W0,W1,W2 transposed hi/lo ---------------
__global__ void wsplit_k(const float* __restrict__ W0, const float* __restrict__ W1,
                         const float* __restrict__ W2) {
    int gidx = blockIdx.x * blockDim.x + threadIdx.x;
    if (gidx >= 3 * DD * DD) return;
    int m = gidx / (DD * DD);
    int idx = gidx - m * (DD * DD);
    const float* W = (m == 0) ? W0 : (m == 1) ? W1 : W2;
    int k = idx >> 7, n = idx & 127;
    float w = W[idx];
    __nv_bfloat16 h = __float2bfloat16_rn(w);
    float hf = __bfloat162float(h);
    __nv_bfloat16 l = __float2bfloat16_rn(w - hf);
    g_wth[m * DD * DD + n * DD + k] = __bfloat16_as_ushort(h);
    g_wtl[m * DD * DD + n * DD + k] = __bfloat16_as_ushort(l);
}

// ---------------- Wvo = Wv @ Wo (slot 3), bvo = bv @ Wo + bo ---------------------
__global__ void wvo_k(const float* __restrict__ Wv, const float* __restrict__ bv,
                      const float* __restrict__ Wo, const float* __restrict__ bo) {
    __shared__ float rowv[128];
    int t = threadIdx.x;
    if (blockIdx.x < 128) {
        int i = blockIdx.x;
        rowv[t] = Wv[i * 128 + t];
        __syncthreads();
        float s = 0.0f;
        #pragma unroll 8
        for (int k = 0; k < 128; k++) s += rowv[k] * Wo[k * 128 + t];
        __nv_bfloat16 h = __float2bfloat16_rn(s);
        float hf = __bfloat162float(h);
        __nv_bfloat16 l = __float2bfloat16_rn(s - hf);
        g_wth[3 * DD * DD + t * DD + i] = __bfloat16_as_ushort(h);
        g_wtl[3 * DD * DD + t * DD + i] = __bfloat16_as_ushort(l);
    } else {
        float s = bo[t];
        #pragma unroll 8
        for (int k = 0; k < 128; k++) s += bv[k] * Wo[k * 128 + t];
        g_bvo[t] = s;
    }
}

// ---------------- tensor-core GEMM (fused prologue/epilogue variants) ------------
//  - Ain16 != null: prologue input comes from the fp16 buffer (conv-agg output).
//  - Res != null  : a = relu(in*scale+shift) + Res (BN apply), stored to Store.
//  - lng != null  : LayerNorm epilogue: C = LN(Store + acc + bias) per row.
//  - C == null    : skip fp32 output write; C16 != null: write half2 shadow copy.

__device__ __forceinline__ unsigned pack_bf16x2(float lo_elem, float hi_elem) {
    unsigned r;
    asm("cvt.rn.bf16x2.f32 %0, %1, %2;" : "=r"(r) : "f"(hi_elem), "f"(lo_elem));
    return r;
}

__device__ __forceinline__ void mma16816(float* c, const unsigned* a,
                                         unsigned b0, unsigned b1) {
    asm volatile(
        "mma.sync.aligned.m16n8k16.row.col.f32.bf16.bf16.f32 "
        "{%0,%1,%2,%3}, {%4,%5,%6,%7}, {%8,%9}, {%0,%1,%2,%3};"
        : "+f"(c[0]), "+f"(c[1]), "+f"(c[2]), "+f"(c[3])
        : "r"(a[0]), "r"(a[1]), "r"(a[2]), "r"(a[3]), "r"(b0), "r"(b1));
}

__device__ __forceinline__ void split2(float2 x, unsigned& hi, unsigned& lo) {
    hi = pack_bf16x2(x.x, x.y);
    float h0 = __uint_as_float(hi << 16);
    float h1 = __uint_as_float(hi & 0xFFFF0000u);
    lo = pack_bf16x2(x.x - h0, x.y - h1);
}

#define WT_STRIDE 68

__global__ __launch_bounds__(256) void gemm_tc(
    const float* __restrict__ Ain, const __half2* __restrict__ Ain16,
    const float* __restrict__ Res, float* __restrict__ Store,
    const unsigned short* __restrict__ Wthi, const unsigned short* __restrict__ Wtlo,
    const float* __restrict__ bias,
    const float* __restrict__ lng, const float* __restrict__ lnb,
    float* __restrict__ C, __half2* __restrict__ C16, int M)
{
    extern __shared__ unsigned smw[];
    unsigned* WhiS = smw;
    unsigned* WloS = smw + DD * WT_STRIDE;
    float* sSc = (float*)(smw + 2 * DD * WT_STRIDE);
    float* sSh = sSc + DD;

    int tid = threadIdx.x;
    const unsigned* ghi = (const unsigned*)Wthi;
    const unsigned* glo = (const unsigned*)Wtlo;
    #pragma unroll
    for (int i = tid; i < DD * 64; i += 256) {
        int n = i >> 6, kw = i & 63;
        WhiS[n * WT_STRIDE + kw] = ghi[i];
        WloS[n * WT_STRIDE + kw] = glo[i];
    }
    if (Res && tid < 128) { sSc[tid] = g_scale[tid]; sSh[tid] = g_shift[tid]; }
    __syncthreads();

    int warp = tid >> 5, lane = tid & 31;
    int g = lane >> 2, tig = lane & 3;
    int row0 = blockIdx.x * 128 + warp * 16 + g;
    int row1 = row0 + 8;
    bool v0 = row0 < M, v1 = row1 < M;
    const float* ar0 = Ain ? Ain + (size_t)row0 * DD : nullptr;
    const float* ar1 = Ain ? Ain + (size_t)row1 * DD : nullptr;
    const __half2* ah0 = Ain16 ? Ain16 + (size_t)row0 * 64 : nullptr;
    const __half2* ah1 = Ain16 ? Ain16 + (size_t)row1 * 64 : nullptr;

    float acc[16][4];
    #pragma unroll
    for (int nt = 0; nt < 16; nt++)
        #pragma unroll
        for (int i = 0; i < 4; i++) acc[nt][i] = 0.0f;

    const float2 z2 = make_float2(0.f, 0.f);

    #pragma unroll
    for (int kc = 0; kc < 8; kc++) {
        int k0 = kc * 16 + 2 * tig;
        float2 x0, x1, x2, x3;
        if (Ain16) {
            x0 = v0 ? __half22float2(ah0[(k0 >> 1)])     : z2;
            x1 = v1 ? __half22float2(ah1[(k0 >> 1)])     : z2;
            x2 = v0 ? __half22float2(ah0[(k0 >> 1) + 4]) : z2;
            x3 = v1 ? __half22float2(ah1[(k0 >> 1) + 4]) : z2;
        } else {
            x0 = v0 ? *(const float2*)(ar0 + k0)     : z2;
            x1 = v1 ? *(const float2*)(ar1 + k0)     : z2;
            x2 = v0 ? *(const float2*)(ar0 + k0 + 8) : z2;
            x3 = v1 ? *(const float2*)(ar1 + k0 + 8) : z2;
        }

        if (Res) {
            float2 scA = make_float2(sSc[k0], sSc[k0 + 1]);
            float2 shA = make_float2(sSh[k0], sSh[k0 + 1]);
            float2 scB = make_float2(sSc[k0 + 8], sSc[k0 + 9]);
            float2 shB = make_float2(sSh[k0 + 8], sSh[k0 + 9]);
            float2 r0 = v0 ? *(const float2*)(Res + (size_t)row0 * DD + k0)     : z2;
            float2 r1 = v1 ? *(const float2*)(Res + (size_t)row1 * DD + k0)     : z2;
            float2 r2 = v0 ? *(const float2*)(Res + (size_t)row0 * DD + k0 + 8) : z2;
            float2 r3 = v1 ? *(const float2*)(Res + (size_t)row1 * DD + k0 + 8) : z2;
            x0.x = fmaxf(fmaf(x0.x, scA.x, shA.x), 0.f) + r0.x;
            x0.y = fmaxf(fmaf(x0.y, scA.y, shA.y), 0.f) + r0.y;
            x1.x = fmaxf(fmaf(x1.x, scA.x, shA.x), 0.f) + r1.x;
            x1.y = fmaxf(fmaf(x1.y, scA.y, shA.y), 0.f) + r1.y;
            x2.x = fmaxf(fmaf(x2.x, scB.x, shB.x), 0.f) + r2.x;
            x2.y = fmaxf(fmaf(x2.y, scB.y, shB.y), 0.f) + r2.y;
            x3.x = fmaxf(fmaf(x3.x, scB.x, shB.x), 0.f) + r3.x;
            x3.y = fmaxf(fmaf(x3.y, scB.y, shB.y), 0.f) + r3.y;
            if (v0) {
                *(float2*)(Store + (size_t)row0 * DD + k0)     = x0;
                *(float2*)(Store + (size_t)row0 * DD + k0 + 8) = x2;
            }
            if (v1) {
                *(float2*)(Store + (size_t)row1 * DD + k0)     = x1;
                *(float2*)(Store + (size_t)row1 * DD + k0 + 8) = x3;
            }
        }

        unsigned ahi[4], alo[4];
        split2(x0, ahi[0], alo[0]);
        split2(x1, ahi[1], alo[1]);
        split2(x2, ahi[2], alo[2]);
        split2(x3, ahi[3], alo[3]);

        int kw = kc * 8 + tig;
        #pragma unroll
        for (int nt = 0; nt < 16; nt++) {
            int nrow = (nt * 8 + g) * WT_STRIDE + kw;
            unsigned bh0 = WhiS[nrow];
            unsigned bh1 = WhiS[nrow + 4];
            unsigned bl0 = WloS[nrow];
            unsigned bl1 = WloS[nrow + 4];
            mma16816(acc[nt], ahi, bh0, bh1);
            mma16816(acc[nt], ahi, bl0, bl1);
            mma16816(acc[nt], alo, bh0, bh1);
        }
    }

    if (!lng) {
        #pragma unroll
        for (int nt = 0; nt < 16; nt++) {
            int col = nt * 8 + 2 * tig;
            float2 bb = bias ? *(const float2*)(bias + col) : z2;
            float o0 = acc[nt][0] + bb.x, o1 = acc[nt][1] + bb.y;
            float o2 = acc[nt][2] + bb.x, o3 = acc[nt][3] + bb.y;
            if (v0) {
                if (C)   *(float2*)(C + (size_t)row0 * DD + col) = make_float2(o0, o1);
                if (C16) C16[(size_t)row0 * 64 + (col >> 1)] = __floats2half2_rn(o0, o1);
            }
            if (v1) {
                if (C)   *(float2*)(C + (size_t)row1 * DD + col) = make_float2(o2, o3);
                if (C16) C16[(size_t)row1 * 64 + (col >> 1)] = __floats2half2_rn(o2, o3);
            }
        }
    } else {
        // LayerNorm epilogue: v = Store(row) + acc + bias; LN across row (quad reduce)
        float s0 = 0.f, q0 = 0.f, s1 = 0.f, q1 = 0.f;
        #pragma unroll
        for (int nt = 0; nt < 16; nt++) {
            int col = nt * 8 + 2 * tig;
            float2 bb = *(const float2*)(bias + col);
            float2 h0 = v0 ? *(const float2*)(Store + (size_t)row0 * DD + col) : z2;
            float2 h1 = v1 ? *(const float2*)(Store + (size_t)row1 * DD + col) : z2;
            float v00 = h0.x + acc[nt][0] + bb.x;
            float v01 = h0.y + acc[nt][1] + bb.y;
            float v10 = h1.x + acc[nt][2] + bb.x;
            float v11 = h1.y + acc[nt][3] + bb.y;
            s0 += v00 + v01; q0 += v00 * v00 + v01 * v01;
            s1 += v10 + v11; q1 += v10 * v10 + v11 * v11;
        }
        #pragma unroll
        for (int o = 1; o <= 2; o <<= 1) {
            s0 += __shfl_xor_sync(0xFFFFFFFFu, s0, o);
            q0 += __shfl_xor_sync(0xFFFFFFFFu, q0, o);
            s1 += __shfl_xor_sync(0xFFFFFFFFu, s1, o);
            q1 += __shfl_xor_sync(0xFFFFFFFFu, q1, o);
        }
        float mu0 = s0 * (1.0f / 128.0f);
        float mu1 = s1 * (1.0f / 128.0f);
        float rs0 = rsqrtf(q0 * (1.0f / 128.0f) - mu0 * mu0 + 1e-5f);
        float rs1 = rsqrtf(q1 * (1.0f / 128.0f) - mu1 * mu1 + 1e-5f);
        #pragma unroll
        for (int nt = 0; nt < 16; nt++) {
            int col = nt * 8 + 2 * tig;
            float2 bb = *(const float2*)(bias + col);
            float2 gg = *(const float2*)(lng + col);
            float2 bt = *(const float2*)(lnb + col);
            if (v0) {
                float2 h0 = *(const float2*)(Store + (size_t)row0 * DD + col);
                float v00 = h0.x + acc[nt][0] + bb.x;
                float v01 = h0.y + acc[nt][1] + bb.y;
                *(float2*)(C + (size_t)row0 * DD + col) =
                    make_float2((v00 - mu0) * rs0 * gg.x + bt.x,
                                (v01 - mu0) * rs0 * gg.y + bt.y);
            }
            if (v1) {
                float2 h1 = *(const float2*)(Store + (size_t)row1 * DD + col);
                float v10 = h1.x + acc[nt][2] + bb.x;
                float v11 = h1.y + acc[nt][3] + bb.y;
                *(float2*)(C + (size_t)row1 * DD + col) =
                    make_float2((v10 - mu1) * rs1 * gg.x + bt.x,
                                (v11 - mu1) * rs1 * gg.y + bt.y);
            }
        }
    }
}

// ---------------- aggregation: warp per node, 8-wide edge unroll ----------------
// out32 != null: fp32 output. out16 != null: fp16 output. doStats: BN partials.
__global__ __launch_bounds__(256) void agg_k(
    const uint2* __restrict__ h16, const float* __restrict__ bias,
    float* __restrict__ out32, uint2* __restrict__ out16, int doStats)
{
    __shared__ float sPart[8][DD];
    int w = threadIdx.x >> 5;
    int n = blockIdx.x * 8 + w;          // grid exactly covers NN
    int l = threadIdx.x & 31;

    float di = g_dinv[n];
    float dii = di * di;
    uint2 us = h16[(size_t)n * 32 + l];
    float2 sa = __half22float2(*(const __half2*)&us.x);
    float2 sb = __half22float2(*(const __half2*)&us.y);
    float4 bb = *(const float4*)(bias + 4 * l);
    float a0 = fmaf(sa.x, dii, bb.x);
    float a1 = fmaf(sa.y, dii, bb.y);
    float a2 = fmaf(sb.x, dii, bb.z);
    float a3 = fmaf(sb.y, dii, bb.w);

    int j = g_off[n], e = g_off[n + 1];
    for (; j + 8 <= e; j += 8) {
        uint2 ed[8], u[8];
        #pragma unroll
        for (int q = 0; q < 8; q++) ed[q] = g_edge[j + q];
        #pragma unroll
        for (int q = 0; q < 8; q++) u[q] = h16[(size_t)ed[q].x * 32 + l];
        #pragma unroll
        for (int q = 0; q < 8; q++) {
            float wq = __uint_as_float(ed[q].y);
            float2 fa = __half22float2(*(const __half2*)&u[q].x);
            float2 fb = __half22float2(*(const __half2*)&u[q].y);
            a0 = fmaf(fa.x, wq, a0); a1 = fmaf(fa.y, wq, a1);
            a2 = fmaf(fb.x, wq, a2); a3 = fmaf(fb.y, wq, a3);
        }
    }
    for (; j < e; ++j) {
        uint2 ed = g_edge[j];
        float wq = __uint_as_float(ed.y);
        uint2 u = h16[(size_t)ed.x * 32 + l];
        float2 fa = __half22float2(*(const __half2*)&u.x);
        float2 fb = __half22float2(*(const __half2*)&u.y);
        a0 = fmaf(fa.x, wq, a0); a1 = fmaf(fa.y, wq, a1);
        a2 = fmaf(fb.x, wq, a2); a3 = fmaf(fb.y, wq, a3);
    }
    if (out32) *(float4*)(out32 + (size_t)n * DD + 4 * l) = make_float4(a0, a1, a2, a3);
    if (out16) {
        __half2 p0 = __floats2half2_rn(a0, a1);
        __half2 p1 = __floats2half2_rn(a2, a3);
        uint2 pk;
        pk.x = *(const unsigned*)&p0;
        pk.y = *(const unsigned*)&p1;
        out16[(size_t)n * 32 + l] = pk;
    }

    if (doStats) {
        *(float4*)&sPart[w][4 * l] = make_float4(a0, a1, a2, a3);
        __syncthreads();
        int t = threadIdx.x;
        if (t < DD) {
            float s = 0.f, q = 0.f;
            #pragma unroll
            for (int ww = 0; ww < 8; ww++) {
                float v = sPart[ww][t];
                s += v; q += v * v;
            }
            g_psum[blockIdx.x * DD + t] = s;
            g_psq[blockIdx.x * DD + t]  = q;
        }
    }
}

// ------- BN stat reduction (single kernel, last-block finishes scale/shift) ------
__global__ void reduce_bn_k(const float* __restrict__ g, const float* __restrict__ be) {
    int b = blockIdx.x;       // 0..127
    int t = threadIdx.x;      // 0..127
    int start = b * 98;
    int end = start + 98; if (end > AGG_BLOCKS) end = AGG_BLOCKS;
    float s = 0.f, q = 0.f;
    for (int p = start; p < end; p++) {
        s += g_psum[p * DD + t];
        q += g_psq[p * DD + t];
    }
    g_psum2[b * DD + t] = s;
    g_psq2[b * DD + t]  = q;
    __threadfence();
    __shared__ int isLast;
    __syncthreads();
    if (t == 0) isLast = (atomicAdd(&g_tick, 1) == 127);
    __syncthreads();
    if (isLast) {
        float ss = 0.f, qq = 0.f;
        for (int p = 0; p < 128; p++) {
            ss += g_psum2[p * DD + t];
            qq += g_psq2[p * DD + t];
        }
        float mu  = ss * (1.0f / NN);
        float var = qq * (1.0f / NN) - mu * mu;
        float sc  = g[t] * rsqrtf(var + 1e-5f);
        g_scale[t] = sc;
        g_shift[t] = be[t] - mu * sc;
        if (t == 0) g_tick = 0;
    }
}

// ---------------- launch ----------------
extern "C" void kernel_launch(void* const* d_in, const int* in_sizes, int n_in,
                              void* d_out, int out_size) {
    const float* x  = (const float*)d_in[0];
    const int*   ei = (const int*)d_in[1];   // int32 (JAX x64-disabled)
    const float* W0 = (const float*)d_in[2];  const float* b0 = (const float*)d_in[3];
    const float* W1 = (const float*)d_in[4];  const float* b1 = (const float*)d_in[5];
    const float* W2 = (const float*)d_in[6];  const float* b2 = (const float*)d_in[7];
    const float* g0 = (const float*)d_in[8];  const float* be0 = (const float*)d_in[9];
    const float* g1 = (const float*)d_in[10]; const float* be1 = (const float*)d_in[11];
    const float* Wv = (const float*)d_in[12]; const float* bv = (const float*)d_in[13];
    const float* Wo = (const float*)d_in[14]; const float* bo = (const float*)d_in[15];
    const float* lng = (const float*)d_in[16]; const float* lnb = (const float*)d_in[17];
    float* out = (float*)d_out;

    void *pA, *pC, *pH, *pB16, *pWh, *pWl, *pBvo;
    cudaGetSymbolAddress(&pA, g_bufA);
    cudaGetSymbolAddress(&pC, g_bufC);
    cudaGetSymbolAddress(&pH, g_h16);
    cudaGetSymbolAddress(&pB16, g_b16);
    cudaGetSymbolAddress(&pWh, g_wth);
    cudaGetSymbolAddress(&pWl, g_wtl);
    cudaGetSymbolAddress(&pBvo, g_bvo);
    float* A = (float*)pA;
    float* C = (float*)pC;
    __half2* H16 = (__half2*)pH;
    const uint2* H16u = (const uint2*)pH;
    uint2* B16u = (uint2*)pB16;
    const __half2* B16h = (const __half2*)pB16;
    const unsigned short* Wh = (const unsigned short*)pWh;
    const unsigned short* Wl = (const unsigned short*)pWl;
    const float* bvo = (const float*)pBvo;

    const int* rowp = ei;
    const int* colp = ei + EE;

    const int SCAN_BLOCKS = (NN + 1023) / 1024;   // 98
    const int GEMM_BLOCKS = (NN + 127) / 128;     // 782
    const int SMEM_W = 2 * DD * WT_STRIDE * 4 + 2 * DD * 4;   // 70656 B

    static int s_init = 0;
    static cudaStream_t s1, s2;
    static cudaEvent_t eFork, eJoin1, eJoin2;
    if (!s_init) {
        cudaFuncSetAttribute(gemm_tc, cudaFuncAttributeMaxDynamicSharedMemorySize, SMEM_W);
        cudaStreamCreateWithFlags(&s1, cudaStreamNonBlocking);
        cudaStreamCreateWithFlags(&s2, cudaStreamNonBlocking);
        cudaEventCreateWithFlags(&eFork, cudaEventDisableTiming);
        cudaEventCreateWithFlags(&eJoin1, cudaEventDisableTiming);
        cudaEventCreateWithFlags(&eJoin2, cudaEventDisableTiming);
        s_init = 1;
    }

    // --- fork: graph prep on s1, weight prep on s2, GEMM0 on main after weights ---
    cudaEventRecord(eFork, 0);
    cudaStreamWaitEvent(s1, eFork, 0);
    cudaStreamWaitEvent(s2, eFork, 0);

    zero_counts_k<<<(NN + 255) / 256, 256, 0, s1>>>();
    hist_k<<<2048, 256, 0, s1>>>(colp);
    scan1_k<<<SCAN_BLOCKS, 1024, 0, s1>>>();
    scan2_k<<<1, 128, 0, s1>>>(SCAN_BLOCKS);
    scan3_k<<<SCAN_BLOCKS, 1024, 0, s1>>>();
    scatter_k<<<2048, 256, 0, s1>>>(rowp, colp);
    cudaEventRecord(eJoin1, s1);

    wsplit_k<<<(3 * DD * DD + 255) / 256, 256, 0, s2>>>(W0, W1, W2);
    wvo_k<<<129, 128, 0, s2>>>(Wv, bv, Wo, bo);
    cudaEventRecord(eJoin2, s2);

    const unsigned short* Wh0 = Wh;               const unsigned short* Wl0 = Wl;
    const unsigned short* Wh1 = Wh + 1 * DD * DD; const unsigned short* Wl1 = Wl + 1 * DD * DD;
    const unsigned short* Wh2 = Wh + 2 * DD * DD; const unsigned short* Wl2 = Wl + 2 * DD * DD;
    const unsigned short* Whv = Wh + 3 * DD * DD; const unsigned short* Wlv = Wl + 3 * DD * DD;

    // --- layer 0: h16 = fp16(x@W0)  (waits on weight prep only) ---
    cudaStreamWaitEvent(0, eJoin2, 0);
    gemm_tc<<<GEMM_BLOCKS, 256, SMEM_W>>>(x, nullptr, nullptr, nullptr, Wh0, Wl0,
                                          nullptr, nullptr, nullptr, nullptr, H16, NN);
    // agg needs the CSR too
    cudaStreamWaitEvent(0, eJoin1, 0);
    agg_k<<<AGG_BLOCKS, 256>>>(H16u, b0, nullptr, B16u, 1);
    reduce_bn_k<<<128, 128>>>(g0, be0);

    // --- layer 1: BN0 apply fused in prologue (C = layer0 out), h16 = fp16(C@W1) --
    gemm_tc<<<GEMM_BLOCKS, 256, SMEM_W>>>(nullptr, B16h, x, C, Wh1, Wl1,
                                          nullptr, nullptr, nullptr, nullptr, H16, NN);
    agg_k<<<AGG_BLOCKS, 256>>>(H16u, b1, nullptr, B16u, 1);
    reduce_bn_k<<<128, 128>>>(g1, be1);

    // --- attention + LN: H = relu(bn(B16))+C (stored to A); att = H@Wvo + bvo ;
    //     C = LN(H + att) ---
    gemm_tc<<<GEMM_BLOCKS, 256, SMEM_W>>>(nullptr, B16h, C, A, Whv, Wlv,
                                          bvo, lng, lnb, C, nullptr, NN);

    // --- output conv: h16 = fp16(C@W2) ; out = agg(h16) ---
    gemm_tc<<<GEMM_BLOCKS, 256, SMEM_W>>>(C, nullptr, nullptr, nullptr, Wh2, Wl2,
                                          nullptr, nullptr, nullptr, nullptr, H16, NN);
    agg_k<<<AGG_BLOCKS, 256>>>(H16u, b2, out, nullptr, 0);
}